// round 8
// baseline (speedup 1.0000x reference)
#include <cuda_runtime.h>
#include <cuda_bf16.h>
#include <cstdint>

// Fixed shapes: B=4, S=1024, E=1024, width=768 -> H=12, D=64
#define Bq   4
#define Sq   1024
#define Eq   1024
#define Wd   768
#define Hh   12
#define Dd   64
#define BSq  (Bq*Sq)            // 4096
#define NZ   (Bq*Hh)            // 48
#define WW   (Wd*Wd)            // 589824
#define OUT_ELEMS   ((long long)BSq*Wd)
#define ATTN_ELEMS  ((long long)NZ*Sq*Sq)

// ---------------- scratch (device globals; no runtime allocation) ----------
__device__ __align__(16) ushort g_xh[BSq*Wd], g_xl[BSq*Wd];
__device__ __align__(16) ushort g_wh[4*WW],  g_wl[4*WW];
__device__ __align__(16) ushort g_qh[BSq*Wd], g_ql[BSq*Wd];
__device__ __align__(16) ushort g_kh[BSq*Wd], g_kl[BSq*Wd];
__device__ __align__(16) ushort g_vh[BSq*Wd], g_vl[BSq*Wd];
__device__ __align__(16) ushort g_ch[BSq*Wd], g_cl[BSq*Wd];
__device__ __align__(16) float g_rm[NZ*Sq];
__device__ __align__(16) float g_ri[NZ*Sq];
__device__ __align__(16) float g_attn_fallback[NZ*Sq*Sq];

// ======================= mma/ldmatrix primitives ===========================
__device__ __forceinline__ void ldsm_x4(uint32_t* r, uint32_t addr) {
    asm volatile("ldmatrix.sync.aligned.m8n8.x4.shared.b16 {%0,%1,%2,%3}, [%4];"
        : "=r"(r[0]), "=r"(r[1]), "=r"(r[2]), "=r"(r[3]) : "r"(addr));
}
__device__ __forceinline__ void ldsm_x4_t(uint32_t* r, uint32_t addr) {
    asm volatile("ldmatrix.sync.aligned.m8n8.x4.trans.shared.b16 {%0,%1,%2,%3}, [%4];"
        : "=r"(r[0]), "=r"(r[1]), "=r"(r[2]), "=r"(r[3]) : "r"(addr));
}
__device__ __forceinline__ void mma_bf16(float* c, const uint32_t* a,
                                         uint32_t b0, uint32_t b1) {
    asm volatile("mma.sync.aligned.m16n8k16.row.col.f32.bf16.bf16.f32 "
        "{%0,%1,%2,%3}, {%4,%5,%6,%7}, {%8,%9}, {%0,%1,%2,%3};"
        : "+f"(c[0]), "+f"(c[1]), "+f"(c[2]), "+f"(c[3])
        : "r"(a[0]), "r"(a[1]), "r"(a[2]), "r"(a[3]), "r"(b0), "r"(b1));
}
__device__ __forceinline__ void split_bf(float v, ushort& h, ushort& l) {
    __nv_bfloat16 hh = __float2bfloat16(v);
    h = __bfloat16_as_ushort(hh);
    l = __bfloat16_as_ushort(__float2bfloat16(v - __bfloat162float(hh)));
}

// ===========================================================================
// conv_kernel: fp32 (stride 1024) -> bf16 hi/lo (stride 768), once.
// grid.y: 0=query(4096 rows), 1..4 = q_w,k_w,v_w,o_w (768 rows each)
// ===========================================================================
__global__ __launch_bounds__(256)
void conv_kernel(const float* __restrict__ x,
                 const float* __restrict__ qw, const float* __restrict__ kw,
                 const float* __restrict__ vw, const float* __restrict__ ow) {
    const int z = blockIdx.y;
    const float* src; ushort* dh; ushort* dl; int rows;
    if (z == 0)      { src = x;  dh = g_xh;          dl = g_xl;          rows = BSq; }
    else if (z == 1) { src = qw; dh = g_wh;          dl = g_wl;          rows = Wd; }
    else if (z == 2) { src = kw; dh = g_wh + WW;     dl = g_wl + WW;     rows = Wd; }
    else if (z == 3) { src = vw; dh = g_wh + 2*WW;   dl = g_wl + 2*WW;   rows = Wd; }
    else             { src = ow; dh = g_wh + 3*WW;   dl = g_wl + 3*WW;   rows = Wd; }

    const int idx = blockIdx.x * 256 + threadIdx.x;   // element pair index
    const int total = rows * (Wd / 2);
    if (idx >= total) return;
    const int row = idx / (Wd / 2);
    const int c2 = (idx - row * (Wd / 2)) * 2;
    float2 v = *(const float2*)(src + (size_t)row * Eq + c2);
    ushort h0, l0, h1, l1;
    split_bf(v.x, h0, l0);
    split_bf(v.y, h1, l1);
    *(ushort2*)(dh + (size_t)row * Wd + c2) = make_ushort2(h0, h1);
    *(ushort2*)(dl + (size_t)row * Wd + c2) = make_ushort2(l0, l1);
}

// ===========================================================================
// proj_mma: bf16x3 HMMA GEMM, bf16 inputs from globals.
// mode 0: A=g_x*, W by z -> q/k/v bf16 hi/lo out (bias in fp32 then split)
// mode 1: A=g_c*, W=o_w -> fp32 out_ext (+bias)
// tile 128x128, 256 threads, warp tile 32x64, K chunk 16.
// ===========================================================================
#define PP 24   // proj smem pitch (ushorts) = 48B
__device__ __forceinline__ void fill_proj(const ushort* __restrict__ sh,
                                          const ushort* __restrict__ sl,
                                          ushort* __restrict__ hi,
                                          ushort* __restrict__ lo, int t) {
    #pragma unroll
    for (int u = 0; u < 2; u++) {
        const int p = t + u * 256;     // 0..511
        const int row = p >> 2;        // 0..127
        const int c4 = (p & 3) * 4;    // bf16 offset
        *(uint2*)(hi + row * PP + c4) = *(const uint2*)(sh + (size_t)row * Wd + c4);
        *(uint2*)(lo + row * PP + c4) = *(const uint2*)(sl + (size_t)row * Wd + c4);
    }
}

__global__ __launch_bounds__(256)
void proj_mma(int mode, const float* __restrict__ b0, const float* __restrict__ b1,
              const float* __restrict__ b2, float* __restrict__ out_ext) {
    __shared__ ushort Ah[128*PP], Al[128*PP], Bh[128*PP], Bl[128*PP];

    const int t = threadIdx.x;
    const int wid = t >> 5;
    const int lane = t & 31;

    const ushort *Axh, *Axl, *Wxh, *Wxl;
    const float* bias;
    ushort *oh = nullptr, *ol = nullptr;
    if (mode == 1) {
        Axh = g_ch; Axl = g_cl;
        Wxh = g_wh + 3*WW; Wxl = g_wl + 3*WW;
        bias = b0;
    } else {
        Axh = g_xh; Axl = g_xl;
        const int z = blockIdx.z;
        Wxh = g_wh + z*WW; Wxl = g_wl + z*WW;
        bias = (z == 0) ? b0 : (z == 1) ? b1 : b2;
        if (z == 0)      { oh = g_qh; ol = g_ql; }
        else if (z == 1) { oh = g_kh; ol = g_kl; }
        else             { oh = g_vh; ol = g_vl; }
    }

    const int n0 = blockIdx.x * 128;
    const int i0 = blockIdx.y * 128;
    const int wm = (wid & 3) * 32;
    const int wn = (wid >> 2) * 64;

    float acc[2][8][4];
    #pragma unroll
    for (int mi = 0; mi < 2; mi++)
        #pragma unroll
        for (int ni = 0; ni < 8; ni++)
            #pragma unroll
            for (int j = 0; j < 4; j++) acc[mi][ni][j] = 0.f;

    const uint32_t a_base = (uint32_t)__cvta_generic_to_shared(Ah);
    const uint32_t al_base = (uint32_t)__cvta_generic_to_shared(Al);
    const uint32_t b_base = (uint32_t)__cvta_generic_to_shared(Bh);
    const uint32_t bl_base = (uint32_t)__cvta_generic_to_shared(Bl);
    const int frag_row = ((lane >> 3) & 1) * 8 + (lane & 7);
    const int frag_koff = (lane >> 4) * 16;
    const int bfrag_row = ((lane >> 4) & 1) * 8 + (lane & 7);
    const int bfrag_koff = ((lane >> 3) & 1) * 16;

    for (int c = 0; c < 48; c++) {
        const int k0 = c * 16;
        __syncthreads();
        fill_proj(Axh + (size_t)i0 * Wd + k0, Axl + (size_t)i0 * Wd + k0, Ah, Al, t);
        fill_proj(Wxh + (size_t)n0 * Wd + k0, Wxl + (size_t)n0 * Wd + k0, Bh, Bl, t);
        __syncthreads();

        uint32_t ah[2][4], alr[2][4];
        #pragma unroll
        for (int mi = 0; mi < 2; mi++) {
            const uint32_t off = (uint32_t)((wm + mi * 16 + frag_row) * (PP*2) + frag_koff);
            ldsm_x4(ah[mi], a_base + off);
            ldsm_x4(alr[mi], al_base + off);
        }
        #pragma unroll
        for (int g = 0; g < 4; g++) {
            uint32_t bh[4], blr[4];
            const uint32_t off = (uint32_t)((wn + g * 16 + bfrag_row) * (PP*2) + bfrag_koff);
            ldsm_x4(bh, b_base + off);
            ldsm_x4(blr, bl_base + off);
            #pragma unroll
            for (int s = 0; s < 2; s++) {
                #pragma unroll
                for (int mi = 0; mi < 2; mi++) {
                    float* cc = acc[mi][g * 2 + s];
                    mma_bf16(cc, ah[mi],  bh[2*s],  bh[2*s+1]);
                    mma_bf16(cc, ah[mi],  blr[2*s], blr[2*s+1]);
                    mma_bf16(cc, alr[mi], bh[2*s],  bh[2*s+1]);
                }
            }
        }
    }

    #pragma unroll
    for (int mi = 0; mi < 2; mi++) {
        #pragma unroll
        for (int ni = 0; ni < 8; ni++) {
            const int row = i0 + wm + mi * 16 + (lane >> 2);
            const int col = n0 + wn + ni * 8 + (lane & 3) * 2;
            float2 bb = *(const float2*)(bias + col);
            float v0 = acc[mi][ni][0] + bb.x, v1 = acc[mi][ni][1] + bb.y;
            float v2 = acc[mi][ni][2] + bb.x, v3 = acc[mi][ni][3] + bb.y;
            if (mode == 1) {
                *(float2*)(out_ext + (size_t)row * Wd + col) = make_float2(v0, v1);
                *(float2*)(out_ext + (size_t)(row + 8) * Wd + col) = make_float2(v2, v3);
            } else {
                ushort h0,l0,h1,l1,h2,l2,h3,l3;
                split_bf(v0,h0,l0); split_bf(v1,h1,l1);
                split_bf(v2,h2,l2); split_bf(v3,h3,l3);
                *(ushort2*)(oh + (size_t)row * Wd + col) = make_ushort2(h0,h1);
                *(ushort2*)(ol + (size_t)row * Wd + col) = make_ushort2(l0,l1);
                *(ushort2*)(oh + (size_t)(row + 8) * Wd + col) = make_ushort2(h2,h3);
                *(ushort2*)(ol + (size_t)(row + 8) * Wd + col) = make_ushort2(l2,l3);
            }
        }
    }
}

// ===========================================================================
// Attention tiles: straight bf16 copies, pitch 72 ushorts (144B, 16B-aligned)
// ===========================================================================
#define PITCH 72
__device__ __forceinline__ void fill_att(const ushort* __restrict__ sh,
                                         const ushort* __restrict__ sl,
                                         ushort* __restrict__ hi,
                                         ushort* __restrict__ lo, int t, int rows) {
    const int units = rows * 8;
    for (int p = t; p < units; p += 256) {
        const int row = p >> 3;
        const int c8 = (p & 7) * 8;
        *(uint4*)(hi + row * PITCH + c8) = *(const uint4*)(sh + (size_t)row * Wd + c8);
        *(uint4*)(lo + row * PITCH + c8) = *(const uint4*)(sl + (size_t)row * Wd + c8);
    }
}

// ===========================================================================
// stats_mma: streaming QK^T -> per-row (max, 1/sum). grid(8, 48), 256 thr.
// ===========================================================================
#define STATS_SMEM ((2*128 + 2*64) * PITCH * 2)
__global__ __launch_bounds__(256)
void stats_mma(const int* __restrict__ mask) {
    extern __shared__ ushort smem_u[];
    ushort* QH = smem_u;
    ushort* QL = QH + 128 * PITCH;
    ushort* KH = QL + 128 * PITCH;
    ushort* KL = KH + 64 * PITCH;

    const int t = threadIdx.x;
    const int wid = t >> 5;
    const int lane = t & 31;
    const int z = blockIdx.y;
    const int b = z / Hh;
    const int h = z - b * Hh;
    const int i0 = blockIdx.x * 128;
    const int wm = wid * 16;

    const size_t qoff = ((size_t)b * Sq + i0) * Wd + h * Dd;
    const size_t koff = (size_t)b * Sq * Wd + h * Dd;
    const int* mrow = mask + b * Sq;

    fill_att(g_qh + qoff, g_ql + qoff, QH, QL, t, 128);
    __syncthreads();

    const uint32_t qh_base = (uint32_t)__cvta_generic_to_shared(QH);
    const uint32_t ql_base = (uint32_t)__cvta_generic_to_shared(QL);
    const uint32_t kh_base = (uint32_t)__cvta_generic_to_shared(KH);
    const uint32_t kl_base = (uint32_t)__cvta_generic_to_shared(KL);
    const int frag_row = ((lane >> 3) & 1) * 8 + (lane & 7);
    const int frag_koff = (lane >> 4) * 16;
    const int bfrag_row = ((lane >> 4) & 1) * 8 + (lane & 7);
    const int bfrag_koff = ((lane >> 3) & 1) * 16;

    uint32_t qh[4][4], ql[4][4];
    #pragma unroll
    for (int kb = 0; kb < 4; kb++) {
        const uint32_t off = (uint32_t)((wm + frag_row) * (PITCH * 2) + kb * 32 + frag_koff);
        ldsm_x4(qh[kb], qh_base + off);
        ldsm_x4(ql[kb], ql_base + off);
    }

    float m0 = -3.4e38f, s0 = 0.f, m1 = -3.4e38f, s1 = 0.f;

    for (int j0 = 0; j0 < Sq; j0 += 64) {
        __syncthreads();
        fill_att(g_kh + koff + (size_t)j0 * Wd, g_kl + koff + (size_t)j0 * Wd, KH, KL, t, 64);
        __syncthreads();

        #pragma unroll
        for (int p = 0; p < 4; p++) {
            float acc[2][4] = {};
            #pragma unroll
            for (int kb = 0; kb < 4; kb++) {
                uint32_t kh[4], kl[4];
                const uint32_t off = (uint32_t)((p * 16 + bfrag_row) * (PITCH * 2) + kb * 32 + bfrag_koff);
                ldsm_x4(kh, kh_base + off);
                ldsm_x4(kl, kl_base + off);
                #pragma unroll
                for (int s = 0; s < 2; s++) {
                    mma_bf16(acc[s], qh[kb], kh[2*s], kh[2*s+1]);
                    mma_bf16(acc[s], qh[kb], kl[2*s], kl[2*s+1]);
                    mma_bf16(acc[s], ql[kb], kh[2*s], kh[2*s+1]);
                }
            }
            #pragma unroll
            for (int s = 0; s < 2; s++) {
                const int col = j0 + p * 16 + s * 8 + (lane & 3) * 2;
                const int mk0 = __ldg(mrow + col);
                const int mk1 = __ldg(mrow + col + 1);
                float v0 = mk0 ? acc[s][0] * 0.125f : -1e9f;
                float v1 = mk1 ? acc[s][1] * 0.125f : -1e9f;
                float v2 = mk0 ? acc[s][2] * 0.125f : -1e9f;
                float v3 = mk1 ? acc[s][3] * 0.125f : -1e9f;
                float nm0 = fmaxf(m0, fmaxf(v0, v1));
                s0 = s0 * __expf(m0 - nm0) + __expf(v0 - nm0) + __expf(v1 - nm0);
                m0 = nm0;
                float nm1 = fmaxf(m1, fmaxf(v2, v3));
                s1 = s1 * __expf(m1 - nm1) + __expf(v2 - nm1) + __expf(v3 - nm1);
                m1 = nm1;
            }
        }
    }

    #pragma unroll
    for (int off = 1; off < 4; off <<= 1) {
        float mo = __shfl_xor_sync(0xffffffffu, m0, off);
        float so = __shfl_xor_sync(0xffffffffu, s0, off);
        float nm = fmaxf(m0, mo);
        s0 = s0 * __expf(m0 - nm) + so * __expf(mo - nm);
        m0 = nm;
        mo = __shfl_xor_sync(0xffffffffu, m1, off);
        so = __shfl_xor_sync(0xffffffffu, s1, off);
        nm = fmaxf(m1, mo);
        s1 = s1 * __expf(m1 - nm) + so * __expf(mo - nm);
        m1 = nm;
    }
    if ((lane & 3) == 0) {
        const int r = i0 + wm + (lane >> 2);
        g_rm[z * Sq + r] = m0;
        g_ri[z * Sq + r] = 1.0f / s0;
        g_rm[z * Sq + r + 8] = m1;
        g_ri[z * Sq + r + 8] = 1.0f / s1;
    }
}

// ===========================================================================
// av_mma: recompute QK^T, normalize, write P once, fused P@V.
// V kept [key][d]; PV B-fragments via ldmatrix.trans. grid(8,48), 256 thr.
// ===========================================================================
#define AV_SMEM ((2*128 + 4*64) * PITCH * 2)
__global__ __launch_bounds__(256)
void av_mma(const int* __restrict__ mask, float* __restrict__ attn_out) {
    extern __shared__ ushort smem_u[];
    ushort* QH = smem_u;
    ushort* QL = QH + 128 * PITCH;
    ushort* KH = QL + 128 * PITCH;
    ushort* KL = KH + 64 * PITCH;
    ushort* VH = KL + 64 * PITCH;
    ushort* VL = VH + 64 * PITCH;

    float* attnW = attn_out ? attn_out : g_attn_fallback;

    const int t = threadIdx.x;
    const int wid = t >> 5;
    const int lane = t & 31;
    const int z = blockIdx.y;
    const int b = z / Hh;
    const int h = z - b * Hh;
    const int i0 = blockIdx.x * 128;
    const int wm = wid * 16;

    const size_t qoff = ((size_t)b * Sq + i0) * Wd + h * Dd;
    const size_t koff = (size_t)b * Sq * Wd + h * Dd;
    const int* mrow = mask + b * Sq;

    fill_att(g_qh + qoff, g_ql + qoff, QH, QL, t, 128);
    __syncthreads();

    const uint32_t qh_base = (uint32_t)__cvta_generic_to_shared(QH);
    const uint32_t ql_base = (uint32_t)__cvta_generic_to_shared(QL);
    const uint32_t kh_base = (uint32_t)__cvta_generic_to_shared(KH);
    const uint32_t kl_base = (uint32_t)__cvta_generic_to_shared(KL);
    const uint32_t vh_base = (uint32_t)__cvta_generic_to_shared(VH);
    const uint32_t vl_base = (uint32_t)__cvta_generic_to_shared(VL);
    const int frag_row = ((lane >> 3) & 1) * 8 + (lane & 7);
    const int frag_koff = (lane >> 4) * 16;
    const int bfrag_row = ((lane >> 4) & 1) * 8 + (lane & 7);
    const int bfrag_koff = ((lane >> 3) & 1) * 16;
    // trans fragment mapping (FA2 convention): lanes 0-15 -> k rows, 16-31 -> +16B n
    const int tfrag_row = ((lane >> 3) & 1) * 8 + (lane & 7);
    const int tfrag_noff = ((lane >> 4) & 1) * 16;

    uint32_t qh[4][4], ql[4][4];
    #pragma unroll
    for (int kb = 0; kb < 4; kb++) {
        const uint32_t off = (uint32_t)((wm + frag_row) * (PITCH * 2) + kb * 32 + frag_koff);
        ldsm_x4(qh[kb], qh_base + off);
        ldsm_x4(ql[kb], ql_base + off);
    }

    const int r0 = wm + (lane >> 2);
    const float mm0 = g_rm[z * Sq + i0 + r0];
    const float ii0 = g_ri[z * Sq + i0 + r0];
    const float mm1 = g_rm[z * Sq + i0 + r0 + 8];
    const float ii1 = g_ri[z * Sq + i0 + r0 + 8];

    float ctx[8][4];
    #pragma unroll
    for (int ni = 0; ni < 8; ni++)
        #pragma unroll
        for (int j = 0; j < 4; j++) ctx[ni][j] = 0.f;

    float* Prow0 = attnW + ((size_t)z * Sq + i0 + r0) * Sq;
    float* Prow1 = attnW + ((size_t)z * Sq + i0 + r0 + 8) * Sq;

    for (int j0 = 0; j0 < Sq; j0 += 64) {
        __syncthreads();
        fill_att(g_kh + koff + (size_t)j0 * Wd, g_kl + koff + (size_t)j0 * Wd, KH, KL, t, 64);
        fill_att(g_vh + koff + (size_t)j0 * Wd, g_vl + koff + (size_t)j0 * Wd, VH, VL, t, 64);
        __syncthreads();

        #pragma unroll
        for (int p = 0; p < 4; p++) {
            // ---- S tile ----
            float acc[2][4] = {};
            #pragma unroll
            for (int kb = 0; kb < 4; kb++) {
                uint32_t kh[4], kl[4];
                const uint32_t off = (uint32_t)((p * 16 + bfrag_row) * (PITCH * 2) + kb * 32 + bfrag_koff);
                ldsm_x4(kh, kh_base + off);
                ldsm_x4(kl, kl_base + off);
                #pragma unroll
                for (int s = 0; s < 2; s++) {
                    mma_bf16(acc[s], qh[kb], kh[2*s], kh[2*s+1]);
                    mma_bf16(acc[s], qh[kb], kl[2*s], kl[2*s+1]);
                    mma_bf16(acc[s], ql[kb], kh[2*s], kh[2*s+1]);
                }
            }
            // ---- normalize, write P, build P fragments ----
            uint32_t pfh[4], pfl[4];
            #pragma unroll
            for (int s = 0; s < 2; s++) {
                const int col = j0 + p * 16 + s * 8 + (lane & 3) * 2;
                const int mk0 = __ldg(mrow + col);
                const int mk1 = __ldg(mrow + col + 1);
                float v0 = mk0 ? acc[s][0] * 0.125f : -1e9f;
                float v1 = mk1 ? acc[s][1] * 0.125f : -1e9f;
                float v2 = mk0 ? acc[s][2] * 0.125f : -1e9f;
                float v3 = mk1 ? acc[s][3] * 0.125f : -1e9f;
                float p0 = __expf(v0 - mm0) * ii0;
                float p1 = __expf(v1 - mm0) * ii0;
                float p2 = __expf(v2 - mm1) * ii1;
                float p3 = __expf(v3 - mm1) * ii1;
                *(float2*)(Prow0 + col) = make_float2(p0, p1);
                *(float2*)(Prow1 + col) = make_float2(p2, p3);
                ushort h0,l0,h1,l1,h2,l2,h3,l3;
                split_bf(p0,h0,l0); split_bf(p1,h1,l1);
                split_bf(p2,h2,l2); split_bf(p3,h3,l3);
                pfh[s*2+0] = (uint32_t)h0 | ((uint32_t)h1 << 16);
                pfh[s*2+1] = (uint32_t)h2 | ((uint32_t)h3 << 16);
                pfl[s*2+0] = (uint32_t)l0 | ((uint32_t)l1 << 16);
                pfl[s*2+1] = (uint32_t)l2 | ((uint32_t)l3 << 16);
            }
            // ---- P@V (V natural layout; trans ldmatrix for B) ----
            #pragma unroll
            for (int gv = 0; gv < 4; gv++) {
                uint32_t vh[4], vl[4];
                const uint32_t off = (uint32_t)((p * 16 + tfrag_row) * (PITCH * 2) + gv * 32 + tfrag_noff);
                ldsm_x4_t(vh, vh_base + off);
                ldsm_x4_t(vl, vl_base + off);
                #pragma unroll
                for (int s = 0; s < 2; s++) {
                    float* cc = ctx[gv * 2 + s];
                    mma_bf16(cc, pfh, vh[2*s], vh[2*s+1]);
                    mma_bf16(cc, pfh, vl[2*s], vl[2*s+1]);
                    mma_bf16(cc, pfl, vh[2*s], vh[2*s+1]);
                }
            }
        }
    }

    // Epilogue: ctx -> bf16 hi/lo [B,S,W]
    #pragma unroll
    for (int ni = 0; ni < 8; ni++) {
        const int col = (ni >> 1) * 16 + (ni & 1) * 8 + (lane & 3) * 2;
        const size_t o0 = ((size_t)b * Sq + i0 + r0) * Wd + h * Dd + col;
        const size_t o1 = ((size_t)b * Sq + i0 + r0 + 8) * Wd + h * Dd + col;
        ushort h0,l0,h1,l1,h2,l2,h3,l3;
        split_bf(ctx[ni][0],h0,l0); split_bf(ctx[ni][1],h1,l1);
        split_bf(ctx[ni][2],h2,l2); split_bf(ctx[ni][3],h3,l3);
        *(ushort2*)(g_ch + o0) = make_ushort2(h0,h1);
        *(ushort2*)(g_cl + o0) = make_ushort2(l0,l1);
        *(ushort2*)(g_ch + o1) = make_ushort2(h2,h3);
        *(ushort2*)(g_cl + o1) = make_ushort2(l2,l3);
    }
}

// ---------------------------------------------------------------------------
extern "C" void kernel_launch(void* const* d_in, const int* in_sizes, int n_in,
                              void* d_out, int out_size) {
    const float* query = (const float*)d_in[0];
    const int*   mask  = (const int*)d_in[1];
    const float* q_w = (const float*)d_in[2];
    const float* q_b = (const float*)d_in[3];
    const float* k_w = (const float*)d_in[4];
    const float* k_b = (const float*)d_in[5];
    const float* v_w = (const float*)d_in[6];
    const float* v_b = (const float*)d_in[7];
    const float* o_w = (const float*)d_in[8];
    const float* o_b = (const float*)d_in[9];

    float* out = (float*)d_out;
    float* attn = ((long long)out_size >= OUT_ELEMS + ATTN_ELEMS) ? out + OUT_ELEMS : nullptr;

    cudaFuncSetAttribute(stats_mma, cudaFuncAttributeMaxDynamicSharedMemorySize, STATS_SMEM);
    cudaFuncSetAttribute(av_mma, cudaFuncAttributeMaxDynamicSharedMemorySize, AV_SMEM);

    const int conv_blocks = (BSq * (Wd / 2) + 255) / 256;   // enough for the largest (query)
    conv_kernel<<<dim3(conv_blocks, 5), 256>>>(query, q_w, k_w, v_w, o_w);
    proj_mma<<<dim3(6, 32, 3), 256>>>(0, q_b, k_b, v_b, nullptr);
    stats_mma<<<dim3(8, NZ), 256, STATS_SMEM>>>(mask);
    av_mma<<<dim3(8, NZ), 256, AV_SMEM>>>(mask, attn);
    proj_mma<<<dim3(6, 32, 1), 256>>>(1, o_b, nullptr, nullptr, out);
}

// round 9
// speedup vs baseline: 1.1589x; 1.1589x over previous
#include <cuda_runtime.h>
#include <cuda_bf16.h>
#include <cstdint>

// Fixed shapes: B=4, S=1024, E=1024, width=768 -> H=12, D=64
#define Bq   4
#define Sq   1024
#define Eq   1024
#define Wd   768
#define Hh   12
#define Dd   64
#define BSq  (Bq*Sq)
#define NZ   (Bq*Hh)
#define WW   (Wd*Wd)
#define OUT_ELEMS   ((long long)BSq*Wd)
#define ATTN_ELEMS  ((long long)NZ*Sq*Sq)

// ---------------- scratch (device globals; no runtime allocation) ----------
__device__ __align__(16) ushort g_xh[BSq*Wd], g_xl[BSq*Wd];
__device__ __align__(16) ushort g_wh[4*WW],  g_wl[4*WW];
__device__ __align__(16) ushort g_qh[BSq*Wd], g_ql[BSq*Wd];
__device__ __align__(16) ushort g_kh[BSq*Wd], g_kl[BSq*Wd];
__device__ __align__(16) ushort g_vh[BSq*Wd], g_vl[BSq*Wd];
__device__ __align__(16) ushort g_ch[BSq*Wd], g_cl[BSq*Wd];
__device__ __align__(16) float g_rm[NZ*Sq];
__device__ __align__(16) float g_ri[NZ*Sq];
__device__ __align__(16) float g_attn_fallback[NZ*Sq*Sq];

// ======================= primitives ========================================
__device__ __forceinline__ void ldsm_x4(uint32_t* r, uint32_t addr) {
    asm volatile("ldmatrix.sync.aligned.m8n8.x4.shared.b16 {%0,%1,%2,%3}, [%4];"
        : "=r"(r[0]), "=r"(r[1]), "=r"(r[2]), "=r"(r[3]) : "r"(addr));
}
__device__ __forceinline__ void ldsm_x4_t(uint32_t* r, uint32_t addr) {
    asm volatile("ldmatrix.sync.aligned.m8n8.x4.trans.shared.b16 {%0,%1,%2,%3}, [%4];"
        : "=r"(r[0]), "=r"(r[1]), "=r"(r[2]), "=r"(r[3]) : "r"(addr));
}
__device__ __forceinline__ void mma_bf16(float* c, const uint32_t* a,
                                         uint32_t b0, uint32_t b1) {
    asm volatile("mma.sync.aligned.m16n8k16.row.col.f32.bf16.bf16.f32 "
        "{%0,%1,%2,%3}, {%4,%5,%6,%7}, {%8,%9}, {%0,%1,%2,%3};"
        : "+f"(c[0]), "+f"(c[1]), "+f"(c[2]), "+f"(c[3])
        : "r"(a[0]), "r"(a[1]), "r"(a[2]), "r"(a[3]), "r"(b0), "r"(b1));
}
__device__ __forceinline__ void split_bf(float v, ushort& h, ushort& l) {
    __nv_bfloat16 hh = __float2bfloat16(v);
    h = __bfloat16_as_ushort(hh);
    l = __bfloat16_as_ushort(__float2bfloat16(v - __bfloat162float(hh)));
}
__device__ __forceinline__ void cp16(uint32_t dst, const void* src) {
    asm volatile("cp.async.cg.shared.global [%0], [%1], 16;" :: "r"(dst), "l"(src));
}
#define CP_COMMIT() asm volatile("cp.async.commit_group;" ::: "memory")
#define CP_WAIT(n)  asm volatile("cp.async.wait_group %0;" :: "n"(n) : "memory")

// ===========================================================================
// conv_kernel: fp32 (stride 1024) -> bf16 hi/lo (stride 768), once.
// ===========================================================================
__global__ __launch_bounds__(256)
void conv_kernel(const float* __restrict__ x,
                 const float* __restrict__ qw, const float* __restrict__ kw,
                 const float* __restrict__ vw, const float* __restrict__ ow) {
    const int z = blockIdx.y;
    const float* src; ushort* dh; ushort* dl; int rows;
    if (z == 0)      { src = x;  dh = g_xh;        dl = g_xl;        rows = BSq; }
    else if (z == 1) { src = qw; dh = g_wh;        dl = g_wl;        rows = Wd; }
    else if (z == 2) { src = kw; dh = g_wh + WW;   dl = g_wl + WW;   rows = Wd; }
    else if (z == 3) { src = vw; dh = g_wh + 2*WW; dl = g_wl + 2*WW; rows = Wd; }
    else             { src = ow; dh = g_wh + 3*WW; dl = g_wl + 3*WW; rows = Wd; }

    const int idx = blockIdx.x * 256 + threadIdx.x;
    const int total = rows * (Wd / 2);
    if (idx >= total) return;
    const int row = idx / (Wd / 2);
    const int c2 = (idx - row * (Wd / 2)) * 2;
    float2 v = *(const float2*)(src + (size_t)row * Eq + c2);
    ushort h0, l0, h1, l1;
    split_bf(v.x, h0, l0);
    split_bf(v.y, h1, l1);
    *(ushort2*)(dh + (size_t)row * Wd + c2) = make_ushort2(h0, h1);
    *(ushort2*)(dl + (size_t)row * Wd + c2) = make_ushort2(l0, l1);
}

// ===========================================================================
// proj_mma: bf16x3 HMMA GEMM with cp.async double-buffered K chunks.
// ===========================================================================
#define PP 24                         // smem pitch in ushorts (48B)
#define PROJ_TILE (128*PP)            // ushorts per array
#define PROJ_BUF  (4*PROJ_TILE)       // Ah|Al|Bh|Bl
#define PROJ_SMEM (2*PROJ_BUF*2)      // bytes (49152)

__global__ __launch_bounds__(256)
void proj_mma(int mode, const float* __restrict__ b0, const float* __restrict__ b1,
              const float* __restrict__ b2, float* __restrict__ out_ext) {
    extern __shared__ ushort psm[];

    const int t = threadIdx.x;
    const int wid = t >> 5;
    const int lane = t & 31;

    const ushort *Axh, *Axl, *Wxh, *Wxl;
    const float* bias;
    ushort *oh = nullptr, *ol = nullptr;
    if (mode == 1) {
        Axh = g_ch; Axl = g_cl;
        Wxh = g_wh + 3*WW; Wxl = g_wl + 3*WW;
        bias = b0;
    } else {
        Axh = g_xh; Axl = g_xl;
        const int z = blockIdx.z;
        Wxh = g_wh + z*WW; Wxl = g_wl + z*WW;
        bias = (z == 0) ? b0 : (z == 1) ? b1 : b2;
        if (z == 0)      { oh = g_qh; ol = g_ql; }
        else if (z == 1) { oh = g_kh; ol = g_kl; }
        else             { oh = g_vh; ol = g_vl; }
    }

    const int n0 = blockIdx.x * 128;
    const int i0 = blockIdx.y * 128;
    const int wm = (wid & 3) * 32;
    const int wn = (wid >> 2) * 64;

    const uint32_t sb = (uint32_t)__cvta_generic_to_shared(psm);
    const int prow = t >> 1;          // 0..127
    const int pch = t & 1;            // chunk within row (16B)

    const ushort* s4[4] = { Axh + (size_t)(i0 + prow) * Wd,
                            Axl + (size_t)(i0 + prow) * Wd,
                            Wxh + (size_t)(n0 + prow) * Wd,
                            Wxl + (size_t)(n0 + prow) * Wd };

    auto prefetch = [&](int c, int bsel) {
        const uint32_t base = sb + bsel * (PROJ_BUF * 2) + (prow * PP + pch * 8) * 2;
        const int k0 = c * 16;
        #pragma unroll
        for (int u = 0; u < 4; u++)
            cp16(base + u * (PROJ_TILE * 2), s4[u] + k0 + pch * 8);
        CP_COMMIT();
    };

    float acc[2][8][4];
    #pragma unroll
    for (int mi = 0; mi < 2; mi++)
        #pragma unroll
        for (int ni = 0; ni < 8; ni++)
            #pragma unroll
            for (int j = 0; j < 4; j++) acc[mi][ni][j] = 0.f;

    const int frag_row = ((lane >> 3) & 1) * 8 + (lane & 7);
    const int frag_koff = (lane >> 4) * 16;
    const int bfrag_row = ((lane >> 4) & 1) * 8 + (lane & 7);
    const int bfrag_koff = ((lane >> 3) & 1) * 16;

    prefetch(0, 0);

    for (int c = 0; c < 48; c++) {
        if (c + 1 < 48) { prefetch(c + 1, (c + 1) & 1); CP_WAIT(1); }
        else            { CP_WAIT(0); }
        __syncthreads();

        const uint32_t bb = sb + (c & 1) * (PROJ_BUF * 2);
        const uint32_t a_base = bb;
        const uint32_t al_base = bb + PROJ_TILE * 2;
        const uint32_t b_base = bb + 2 * PROJ_TILE * 2;
        const uint32_t bl_base = bb + 3 * PROJ_TILE * 2;

        uint32_t ah[2][4], alr[2][4];
        #pragma unroll
        for (int mi = 0; mi < 2; mi++) {
            const uint32_t off = (uint32_t)((wm + mi * 16 + frag_row) * (PP*2) + frag_koff);
            ldsm_x4(ah[mi], a_base + off);
            ldsm_x4(alr[mi], al_base + off);
        }
        #pragma unroll
        for (int g = 0; g < 4; g++) {
            uint32_t bh[4], blr[4];
            const uint32_t off = (uint32_t)((wn + g * 16 + bfrag_row) * (PP*2) + bfrag_koff);
            ldsm_x4(bh, b_base + off);
            ldsm_x4(blr, bl_base + off);
            #pragma unroll
            for (int s = 0; s < 2; s++) {
                #pragma unroll
                for (int mi = 0; mi < 2; mi++) {
                    float* cc = acc[mi][g * 2 + s];
                    mma_bf16(cc, ah[mi],  bh[2*s],  bh[2*s+1]);
                    mma_bf16(cc, ah[mi],  blr[2*s], blr[2*s+1]);
                    mma_bf16(cc, alr[mi], bh[2*s],  bh[2*s+1]);
                }
            }
        }
        __syncthreads();
    }

    #pragma unroll
    for (int mi = 0; mi < 2; mi++) {
        #pragma unroll
        for (int ni = 0; ni < 8; ni++) {
            const int row = i0 + wm + mi * 16 + (lane >> 2);
            const int col = n0 + wn + ni * 8 + (lane & 3) * 2;
            float2 bb2 = *(const float2*)(bias + col);
            float v0 = acc[mi][ni][0] + bb2.x, v1 = acc[mi][ni][1] + bb2.y;
            float v2 = acc[mi][ni][2] + bb2.x, v3 = acc[mi][ni][3] + bb2.y;
            if (mode == 1) {
                *(float2*)(out_ext + (size_t)row * Wd + col) = make_float2(v0, v1);
                *(float2*)(out_ext + (size_t)(row + 8) * Wd + col) = make_float2(v2, v3);
            } else {
                ushort h0,l0,h1,l1,h2,l2,h3,l3;
                split_bf(v0,h0,l0); split_bf(v1,h1,l1);
                split_bf(v2,h2,l2); split_bf(v3,h3,l3);
                *(ushort2*)(oh + (size_t)row * Wd + col) = make_ushort2(h0,h1);
                *(ushort2*)(ol + (size_t)row * Wd + col) = make_ushort2(l0,l1);
                *(ushort2*)(oh + (size_t)(row + 8) * Wd + col) = make_ushort2(h2,h3);
                *(ushort2*)(ol + (size_t)(row + 8) * Wd + col) = make_ushort2(l2,l3);
            }
        }
    }
}

// ===========================================================================
// Attention smem geometry (pitch 72 ushorts = 144B)
// ===========================================================================
#define PITCH 72
#define QT    (128*PITCH)      // 9216 ushorts per Q array
#define KT    (64*PITCH)       // 4608 ushorts per 64-row array

// Q prefetch: 2 arrays x 128 rows x 8 chunks (bases: qh at sb, ql at sb+QT*2)
__device__ __forceinline__ void prefetch_q(uint32_t sb, const ushort* qh,
                                           const ushort* ql, int t) {
    #pragma unroll
    for (int u = 0; u < 8; u++) {
        const int arr = u >> 2;
        const int rem = ((u & 3) << 8) + t;
        const int row = rem >> 3, ch = rem & 7;
        const ushort* src = (arr == 0 ? qh : ql) + (size_t)row * Wd + ch * 8;
        cp16(sb + (arr * QT + row * PITCH + ch * 8) * 2, src);
    }
    CP_COMMIT();
}

// ===========================================================================
// stats_mma: streaming QK^T -> per-row (max, 1/sum). grid(8,48), 256 thr.
// smem: QH,QL + 2x(KH,KL) + maskadd
// ===========================================================================
#define STATS_KVB (2*KT)                         // ushorts per K buffer
#define STATS_SMEM ((2*QT + 2*STATS_KVB)*2 + Sq*4)
__global__ __launch_bounds__(256)
void stats_mma(const int* __restrict__ mask) {
    extern __shared__ ushort smem_u[];
    float* MA = (float*)(smem_u + 2*QT + 2*STATS_KVB);

    const int t = threadIdx.x;
    const int wid = t >> 5;
    const int lane = t & 31;
    const int z = blockIdx.y;
    const int b = z / Hh;
    const int h = z - b * Hh;
    const int i0 = blockIdx.x * 128;
    const int wm = wid * 16;

    const size_t qoff = ((size_t)b * Sq + i0) * Wd + h * Dd;
    const size_t koff = (size_t)b * Sq * Wd + h * Dd;

    const uint32_t sb = (uint32_t)__cvta_generic_to_shared(smem_u);

    auto prefetch_k = [&](int jt, int bsel) {
        const uint32_t base = sb + (2*QT + bsel * STATS_KVB) * 2;
        const ushort* kh = g_kh + koff + (size_t)jt * 64 * Wd;
        const ushort* kl = g_kl + koff + (size_t)jt * 64 * Wd;
        #pragma unroll
        for (int u = 0; u < 4; u++) {
            const int arr = u >> 1;
            const int rem = ((u & 1) << 8) + t;
            const int row = rem >> 3, ch = rem & 7;
            const ushort* src = (arr == 0 ? kh : kl) + (size_t)row * Wd + ch * 8;
            cp16(base + (arr * KT + row * PITCH + ch * 8) * 2, src);
        }
        CP_COMMIT();
    };

    prefetch_q(sb, g_qh + qoff, g_ql + qoff, t);
    prefetch_k(0, 0);
    #pragma unroll
    for (int i = t; i < Sq; i += 256)
        MA[i] = __ldg(mask + b * Sq + i) ? 0.f : -1e9f;

    CP_WAIT(1);
    __syncthreads();

    const int frag_row = ((lane >> 3) & 1) * 8 + (lane & 7);
    const int frag_koff = (lane >> 4) * 16;
    const int bfrag_row = ((lane >> 4) & 1) * 8 + (lane & 7);
    const int bfrag_koff = ((lane >> 3) & 1) * 16;

    uint32_t qh[4][4], ql[4][4];
    #pragma unroll
    for (int kb = 0; kb < 4; kb++) {
        const uint32_t off = (uint32_t)((wm + frag_row) * (PITCH * 2) + kb * 32 + frag_koff);
        ldsm_x4(qh[kb], sb + off);
        ldsm_x4(ql[kb], sb + QT * 2 + off);
    }

    float m0 = -3.4e38f, s0 = 0.f, m1 = -3.4e38f, s1 = 0.f;

    for (int jt = 0; jt < 16; jt++) {
        if (jt + 1 < 16) { prefetch_k(jt + 1, (jt + 1) & 1); CP_WAIT(1); }
        else             { CP_WAIT(0); }
        __syncthreads();

        const uint32_t kh_base = sb + (2*QT + (jt & 1) * STATS_KVB) * 2;
        const uint32_t kl_base = kh_base + KT * 2;
        const int j0 = jt * 64;

        #pragma unroll
        for (int p = 0; p < 4; p++) {
            float acc[2][4] = {};
            #pragma unroll
            for (int kb = 0; kb < 4; kb++) {
                uint32_t kh[4], kl[4];
                const uint32_t off = (uint32_t)((p * 16 + bfrag_row) * (PITCH * 2) + kb * 32 + bfrag_koff);
                ldsm_x4(kh, kh_base + off);
                ldsm_x4(kl, kl_base + off);
                #pragma unroll
                for (int s = 0; s < 2; s++) {
                    mma_bf16(acc[s], qh[kb], kh[2*s], kh[2*s+1]);
                    mma_bf16(acc[s], qh[kb], kl[2*s], kl[2*s+1]);
                    mma_bf16(acc[s], ql[kb], kh[2*s], kh[2*s+1]);
                }
            }
            #pragma unroll
            for (int s = 0; s < 2; s++) {
                const int col = j0 + p * 16 + s * 8 + (lane & 3) * 2;
                const float ma0 = MA[col], ma1 = MA[col + 1];
                float v0 = acc[s][0] * 0.125f + ma0;
                float v1 = acc[s][1] * 0.125f + ma1;
                float v2 = acc[s][2] * 0.125f + ma0;
                float v3 = acc[s][3] * 0.125f + ma1;
                float nm0 = fmaxf(m0, fmaxf(v0, v1));
                s0 = s0 * __expf(m0 - nm0) + __expf(v0 - nm0) + __expf(v1 - nm0);
                m0 = nm0;
                float nm1 = fmaxf(m1, fmaxf(v2, v3));
                s1 = s1 * __expf(m1 - nm1) + __expf(v2 - nm1) + __expf(v3 - nm1);
                m1 = nm1;
            }
        }
        __syncthreads();
    }

    #pragma unroll
    for (int off = 1; off < 4; off <<= 1) {
        float mo = __shfl_xor_sync(0xffffffffu, m0, off);
        float so = __shfl_xor_sync(0xffffffffu, s0, off);
        float nm = fmaxf(m0, mo);
        s0 = s0 * __expf(m0 - nm) + so * __expf(mo - nm);
        m0 = nm;
        mo = __shfl_xor_sync(0xffffffffu, m1, off);
        so = __shfl_xor_sync(0xffffffffu, s1, off);
        nm = fmaxf(m1, mo);
        s1 = s1 * __expf(m1 - nm) + so * __expf(mo - nm);
        m1 = nm;
    }
    if ((lane & 3) == 0) {
        const int r = i0 + wm + (lane >> 2);
        g_rm[z * Sq + r] = m0;
        g_ri[z * Sq + r] = 1.0f / s0;
        g_rm[z * Sq + r + 8] = m1;
        g_ri[z * Sq + r + 8] = 1.0f / s1;
    }
}

// ===========================================================================
// av_mma: recompute QK^T, normalize, write P once, fused P@V. cp.async DB.
// smem: QH,QL + 2x(KH,KL,VH,VL) + maskadd
// ===========================================================================
#define AV_KVB (4*KT)
#define AV_SMEM ((2*QT + 2*AV_KVB)*2 + Sq*4)
__global__ __launch_bounds__(256)
void av_mma(const int* __restrict__ mask, float* __restrict__ attn_out) {
    extern __shared__ ushort smem_u[];
    float* MA = (float*)(smem_u + 2*QT + 2*AV_KVB);

    float* attnW = attn_out ? attn_out : g_attn_fallback;

    const int t = threadIdx.x;
    const int wid = t >> 5;
    const int lane = t & 31;
    const int z = blockIdx.y;
    const int b = z / Hh;
    const int h = z - b * Hh;
    const int i0 = blockIdx.x * 128;
    const int wm = wid * 16;

    const size_t qoff = ((size_t)b * Sq + i0) * Wd + h * Dd;
    const size_t koff = (size_t)b * Sq * Wd + h * Dd;

    const uint32_t sb = (uint32_t)__cvta_generic_to_shared(smem_u);

    auto prefetch_kv = [&](int jt, int bsel) {
        const uint32_t base = sb + (2*QT + bsel * AV_KVB) * 2;
        const size_t off = koff + (size_t)jt * 64 * Wd;
        const ushort* s4[4] = { g_kh + off, g_kl + off, g_vh + off, g_vl + off };
        #pragma unroll
        for (int u = 0; u < 8; u++) {
            const int arr = u >> 1;
            const int rem = ((u & 1) << 8) + t;
            const int row = rem >> 3, ch = rem & 7;
            cp16(base + (arr * KT + row * PITCH + ch * 8) * 2,
                 s4[arr] + (size_t)row * Wd + ch * 8);
        }
        CP_COMMIT();
    };

    prefetch_q(sb, g_qh + qoff, g_ql + qoff, t);
    prefetch_kv(0, 0);
    #pragma unroll
    for (int i = t; i < Sq; i += 256)
        MA[i] = __ldg(mask + b * Sq + i) ? 0.f : -1e9f;

    CP_WAIT(1);
    __syncthreads();

    const int frag_row = ((lane >> 3) & 1) * 8 + (lane & 7);
    const int frag_koff = (lane >> 4) * 16;
    const int bfrag_row = ((lane >> 4) & 1) * 8 + (lane & 7);
    const int bfrag_koff = ((lane >> 3) & 1) * 16;
    const int tfrag_row = ((lane >> 3) & 1) * 8 + (lane & 7);
    const int tfrag_noff = ((lane >> 4) & 1) * 16;

    uint32_t qh[4][4], ql[4][4];
    #pragma unroll
    for (int kb = 0; kb < 4; kb++) {
        const uint32_t off = (uint32_t)((wm + frag_row) * (PITCH * 2) + kb * 32 + frag_koff);
        ldsm_x4(qh[kb], sb + off);
        ldsm_x4(ql[kb], sb + QT * 2 + off);
    }

    const int r0 = wm + (lane >> 2);
    const float mm0 = g_rm[z * Sq + i0 + r0];
    const float ii0 = g_ri[z * Sq + i0 + r0];
    const float mm1 = g_rm[z * Sq + i0 + r0 + 8];
    const float ii1 = g_ri[z * Sq + i0 + r0 + 8];

    float ctx[8][4];
    #pragma unroll
    for (int ni = 0; ni < 8; ni++)
        #pragma unroll
        for (int j = 0; j < 4; j++) ctx[ni][j] = 0.f;

    float* Prow0 = attnW + ((size_t)z * Sq + i0 + r0) * Sq;
    float* Prow1 = attnW + ((size_t)z * Sq + i0 + r0 + 8) * Sq;

    for (int jt = 0; jt < 16; jt++) {
        if (jt + 1 < 16) { prefetch_kv(jt + 1, (jt + 1) & 1); CP_WAIT(1); }
        else             { CP_WAIT(0); }
        __syncthreads();

        const uint32_t kb0 = sb + (2*QT + (jt & 1) * AV_KVB) * 2;
        const uint32_t kh_base = kb0;
        const uint32_t kl_base = kb0 + KT * 2;
        const uint32_t vh_base = kb0 + 2 * KT * 2;
        const uint32_t vl_base = kb0 + 3 * KT * 2;
        const int j0 = jt * 64;

        #pragma unroll
        for (int p = 0; p < 4; p++) {
            float acc[2][4] = {};
            #pragma unroll
            for (int kb = 0; kb < 4; kb++) {
                uint32_t kh[4], kl[4];
                const uint32_t off = (uint32_t)((p * 16 + bfrag_row) * (PITCH * 2) + kb * 32 + bfrag_koff);
                ldsm_x4(kh, kh_base + off);
                ldsm_x4(kl, kl_base + off);
                #pragma unroll
                for (int s = 0; s < 2; s++) {
                    mma_bf16(acc[s], qh[kb], kh[2*s], kh[2*s+1]);
                    mma_bf16(acc[s], qh[kb], kl[2*s], kl[2*s+1]);
                    mma_bf16(acc[s], ql[kb], kh[2*s], kh[2*s+1]);
                }
            }
            uint32_t pfh[4], pfl[4];
            #pragma unroll
            for (int s = 0; s < 2; s++) {
                const int col = j0 + p * 16 + s * 8 + (lane & 3) * 2;
                const float ma0 = MA[col], ma1 = MA[col + 1];
                float v0 = acc[s][0] * 0.125f + ma0;
                float v1 = acc[s][1] * 0.125f + ma1;
                float v2 = acc[s][2] * 0.125f + ma0;
                float v3 = acc[s][3] * 0.125f + ma1;
                float p0 = __expf(v0 - mm0) * ii0;
                float p1 = __expf(v1 - mm0) * ii0;
                float p2 = __expf(v2 - mm1) * ii1;
                float p3 = __expf(v3 - mm1) * ii1;
                *(float2*)(Prow0 + col) = make_float2(p0, p1);
                *(float2*)(Prow1 + col) = make_float2(p2, p3);
                ushort h0,l0,h1,l1,h2,l2,h3,l3;
                split_bf(p0,h0,l0); split_bf(p1,h1,l1);
                split_bf(p2,h2,l2); split_bf(p3,h3,l3);
                pfh[s*2+0] = (uint32_t)h0 | ((uint32_t)h1 << 16);
                pfh[s*2+1] = (uint32_t)h2 | ((uint32_t)h3 << 16);
                pfl[s*2+0] = (uint32_t)l0 | ((uint32_t)l1 << 16);
                pfl[s*2+1] = (uint32_t)l2 | ((uint32_t)l3 << 16);
            }
            #pragma unroll
            for (int gv = 0; gv < 4; gv++) {
                uint32_t vh[4], vl[4];
                const uint32_t off = (uint32_t)((p * 16 + tfrag_row) * (PITCH * 2) + gv * 32 + tfrag_noff);
                ldsm_x4_t(vh, vh_base + off);
                ldsm_x4_t(vl, vl_base + off);
                #pragma unroll
                for (int s = 0; s < 2; s++) {
                    float* cc = ctx[gv * 2 + s];
                    mma_bf16(cc, pfh, vh[2*s], vh[2*s+1]);
                    mma_bf16(cc, pfh, vl[2*s], vl[2*s+1]);
                    mma_bf16(cc, pfl, vh[2*s], vh[2*s+1]);
                }
            }
        }
        __syncthreads();
    }

    #pragma unroll
    for (int ni = 0; ni < 8; ni++) {
        const int col = (ni >> 1) * 16 + (ni & 1) * 8 + (lane & 3) * 2;
        const size_t o0 = ((size_t)b * Sq + i0 + r0) * Wd + h * Dd + col;
        const size_t o1 = ((size_t)b * Sq + i0 + r0 + 8) * Wd + h * Dd + col;
        ushort h0,l0,h1,l1,h2,l2,h3,l3;
        split_bf(ctx[ni][0],h0,l0); split_bf(ctx[ni][1],h1,l1);
        split_bf(ctx[ni][2],h2,l2); split_bf(ctx[ni][3],h3,l3);
        *(ushort2*)(g_ch + o0) = make_ushort2(h0,h1);
        *(ushort2*)(g_cl + o0) = make_ushort2(l0,l1);
        *(ushort2*)(g_ch + o1) = make_ushort2(h2,h3);
        *(ushort2*)(g_cl + o1) = make_ushort2(l2,l3);
    }
}

// ---------------------------------------------------------------------------
extern "C" void kernel_launch(void* const* d_in, const int* in_sizes, int n_in,
                              void* d_out, int out_size) {
    const float* query = (const float*)d_in[0];
    const int*   mask  = (const int*)d_in[1];
    const float* q_w = (const float*)d_in[2];
    const float* q_b = (const float*)d_in[3];
    const float* k_w = (const float*)d_in[4];
    const float* k_b = (const float*)d_in[5];
    const float* v_w = (const float*)d_in[6];
    const float* v_b = (const float*)d_in[7];
    const float* o_w = (const float*)d_in[8];
    const float* o_b = (const float*)d_in[9];

    float* out = (float*)d_out;
    float* attn = ((long long)out_size >= OUT_ELEMS + ATTN_ELEMS) ? out + OUT_ELEMS : nullptr;

    cudaFuncSetAttribute(proj_mma, cudaFuncAttributeMaxDynamicSharedMemorySize, PROJ_SMEM);
    cudaFuncSetAttribute(stats_mma, cudaFuncAttributeMaxDynamicSharedMemorySize, STATS_SMEM);
    cudaFuncSetAttribute(av_mma, cudaFuncAttributeMaxDynamicSharedMemorySize, AV_SMEM);

    const int conv_blocks = (BSq * (Wd / 2) + 255) / 256;
    conv_kernel<<<dim3(conv_blocks, 5), 256>>>(query, q_w, k_w, v_w, o_w);
    proj_mma<<<dim3(6, 32, 3), 256, PROJ_SMEM>>>(0, q_b, k_b, v_b, nullptr);
    stats_mma<<<dim3(8, NZ), 256, STATS_SMEM>>>(mask);
    av_mma<<<dim3(8, NZ), 256, AV_SMEM>>>(mask, attn);
    proj_mma<<<dim3(6, 32, 1), 256, PROJ_SMEM>>>(1, o_b, nullptr, nullptr, out);
}

// round 10
// speedup vs baseline: 1.2643x; 1.0909x over previous
#include <cuda_runtime.h>
#include <cuda_bf16.h>
#include <cstdint>

// Fixed shapes: B=4, S=1024, E=1024, width=768 -> H=12, D=64
#define Bq   4
#define Sq   1024
#define Eq   1024
#define Wd   768
#define Hh   12
#define Dd   64
#define BSq  (Bq*Sq)
#define NZ   (Bq*Hh)
#define WW   (Wd*Wd)
#define OUT_ELEMS   ((long long)BSq*Wd)
#define ATTN_ELEMS  ((long long)NZ*Sq*Sq)

// ---------------- scratch (device globals; no runtime allocation) ----------
__device__ __align__(16) ushort g_xh[BSq*Wd], g_xl[BSq*Wd];
__device__ __align__(16) ushort g_wh[4*WW],  g_wl[4*WW];
__device__ __align__(16) ushort g_qh[BSq*Wd], g_ql[BSq*Wd];
__device__ __align__(16) ushort g_kh[BSq*Wd], g_kl[BSq*Wd];
__device__ __align__(16) ushort g_vh[BSq*Wd], g_vl[BSq*Wd];
__device__ __align__(16) ushort g_ch[BSq*Wd], g_cl[BSq*Wd];
__device__ __align__(16) float g_rm[NZ*Sq];
__device__ __align__(16) float g_ri[NZ*Sq];
__device__ __align__(16) float g_attn_fallback[NZ*Sq*Sq];

// ======================= primitives ========================================
__device__ __forceinline__ void ldsm_x4(uint32_t* r, uint32_t addr) {
    asm volatile("ldmatrix.sync.aligned.m8n8.x4.shared.b16 {%0,%1,%2,%3}, [%4];"
        : "=r"(r[0]), "=r"(r[1]), "=r"(r[2]), "=r"(r[3]) : "r"(addr));
}
__device__ __forceinline__ void ldsm_x4_t(uint32_t* r, uint32_t addr) {
    asm volatile("ldmatrix.sync.aligned.m8n8.x4.trans.shared.b16 {%0,%1,%2,%3}, [%4];"
        : "=r"(r[0]), "=r"(r[1]), "=r"(r[2]), "=r"(r[3]) : "r"(addr));
}
__device__ __forceinline__ void mma_bf16(float* c, const uint32_t* a,
                                         uint32_t b0, uint32_t b1) {
    asm volatile("mma.sync.aligned.m16n8k16.row.col.f32.bf16.bf16.f32 "
        "{%0,%1,%2,%3}, {%4,%5,%6,%7}, {%8,%9}, {%0,%1,%2,%3};"
        : "+f"(c[0]), "+f"(c[1]), "+f"(c[2]), "+f"(c[3])
        : "r"(a[0]), "r"(a[1]), "r"(a[2]), "r"(a[3]), "r"(b0), "r"(b1));
}
__device__ __forceinline__ void split_bf(float v, ushort& h, ushort& l) {
    __nv_bfloat16 hh = __float2bfloat16(v);
    h = __bfloat16_as_ushort(hh);
    l = __bfloat16_as_ushort(__float2bfloat16(v - __bfloat162float(hh)));
}
__device__ __forceinline__ void cp16(uint32_t dst, const void* src) {
    asm volatile("cp.async.cg.shared.global [%0], [%1], 16;" :: "r"(dst), "l"(src));
}
#define CP_COMMIT() asm volatile("cp.async.commit_group;" ::: "memory")
#define CP_WAIT(n)  asm volatile("cp.async.wait_group %0;" :: "n"(n) : "memory")

// ===========================================================================
// conv_kernel: fp32 (stride 1024) -> bf16 hi/lo (stride 768), once.
// ===========================================================================
__global__ __launch_bounds__(256)
void conv_kernel(const float* __restrict__ x,
                 const float* __restrict__ qw, const float* __restrict__ kw,
                 const float* __restrict__ vw, const float* __restrict__ ow) {
    const int z = blockIdx.y;
    const float* src; ushort* dh; ushort* dl; int rows;
    if (z == 0)      { src = x;  dh = g_xh;        dl = g_xl;        rows = BSq; }
    else if (z == 1) { src = qw; dh = g_wh;        dl = g_wl;        rows = Wd; }
    else if (z == 2) { src = kw; dh = g_wh + WW;   dl = g_wl + WW;   rows = Wd; }
    else if (z == 3) { src = vw; dh = g_wh + 2*WW; dl = g_wl + 2*WW; rows = Wd; }
    else             { src = ow; dh = g_wh + 3*WW; dl = g_wl + 3*WW; rows = Wd; }

    const int idx = blockIdx.x * 256 + threadIdx.x;
    const int total = rows * (Wd / 2);
    if (idx >= total) return;
    const int row = idx / (Wd / 2);
    const int c2 = (idx - row * (Wd / 2)) * 2;
    float2 v = *(const float2*)(src + (size_t)row * Eq + c2);
    ushort h0, l0, h1, l1;
    split_bf(v.x, h0, l0);
    split_bf(v.y, h1, l1);
    *(ushort2*)(dh + (size_t)row * Wd + c2) = make_ushort2(h0, h1);
    *(ushort2*)(dl + (size_t)row * Wd + c2) = make_ushort2(l0, l1);
}

// ===========================================================================
// proj_mma: bf16x3 HMMA GEMM with cp.async double-buffered K chunks.
// ===========================================================================
#define PP 24                         // smem pitch in ushorts (48B)
#define PROJ_TILE (128*PP)            // ushorts per array
#define PROJ_BUF  (4*PROJ_TILE)       // Ah|Al|Bh|Bl
#define PROJ_SMEM (2*PROJ_BUF*2)      // bytes (49152)

__global__ __launch_bounds__(256, 2)
void proj_mma(int mode, const float* __restrict__ b0, const float* __restrict__ b1,
              const float* __restrict__ b2, float* __restrict__ out_ext) {
    extern __shared__ ushort psm[];

    const int t = threadIdx.x;
    const int wid = t >> 5;
    const int lane = t & 31;

    const ushort *Axh, *Axl, *Wxh, *Wxl;
    const float* bias;
    ushort *oh = nullptr, *ol = nullptr;
    if (mode == 1) {
        Axh = g_ch; Axl = g_cl;
        Wxh = g_wh + 3*WW; Wxl = g_wl + 3*WW;
        bias = b0;
    } else {
        Axh = g_xh; Axl = g_xl;
        const int z = blockIdx.z;
        Wxh = g_wh + z*WW; Wxl = g_wl + z*WW;
        bias = (z == 0) ? b0 : (z == 1) ? b1 : b2;
        if (z == 0)      { oh = g_qh; ol = g_ql; }
        else if (z == 1) { oh = g_kh; ol = g_kl; }
        else             { oh = g_vh; ol = g_vl; }
    }

    const int n0 = blockIdx.x * 128;
    const int i0 = blockIdx.y * 128;
    const int wm = (wid & 3) * 32;
    const int wn = (wid >> 2) * 64;

    const uint32_t sb = (uint32_t)__cvta_generic_to_shared(psm);
    const int prow = t >> 1;          // 0..127
    const int pch = t & 1;            // chunk within row (16B)

    const ushort* s4[4] = { Axh + (size_t)(i0 + prow) * Wd,
                            Axl + (size_t)(i0 + prow) * Wd,
                            Wxh + (size_t)(n0 + prow) * Wd,
                            Wxl + (size_t)(n0 + prow) * Wd };

    auto prefetch = [&](int c, int bsel) {
        const uint32_t base = sb + bsel * (PROJ_BUF * 2) + (prow * PP + pch * 8) * 2;
        const int k0 = c * 16;
        #pragma unroll
        for (int u = 0; u < 4; u++)
            cp16(base + u * (PROJ_TILE * 2), s4[u] + k0 + pch * 8);
        CP_COMMIT();
    };

    float acc[2][8][4];
    #pragma unroll
    for (int mi = 0; mi < 2; mi++)
        #pragma unroll
        for (int ni = 0; ni < 8; ni++)
            #pragma unroll
            for (int j = 0; j < 4; j++) acc[mi][ni][j] = 0.f;

    const int frag_row = ((lane >> 3) & 1) * 8 + (lane & 7);
    const int frag_koff = (lane >> 4) * 16;
    const int bfrag_row = ((lane >> 4) & 1) * 8 + (lane & 7);
    const int bfrag_koff = ((lane >> 3) & 1) * 16;

    prefetch(0, 0);

    for (int c = 0; c < 48; c++) {
        if (c + 1 < 48) { prefetch(c + 1, (c + 1) & 1); CP_WAIT(1); }
        else            { CP_WAIT(0); }
        __syncthreads();

        const uint32_t bb = sb + (c & 1) * (PROJ_BUF * 2);
        const uint32_t a_base = bb;
        const uint32_t al_base = bb + PROJ_TILE * 2;
        const uint32_t b_base = bb + 2 * PROJ_TILE * 2;
        const uint32_t bl_base = bb + 3 * PROJ_TILE * 2;

        uint32_t ah[2][4], alr[2][4];
        #pragma unroll
        for (int mi = 0; mi < 2; mi++) {
            const uint32_t off = (uint32_t)((wm + mi * 16 + frag_row) * (PP*2) + frag_koff);
            ldsm_x4(ah[mi], a_base + off);
            ldsm_x4(alr[mi], al_base + off);
        }
        #pragma unroll
        for (int g = 0; g < 4; g++) {
            uint32_t bh[4], blr[4];
            const uint32_t off = (uint32_t)((wn + g * 16 + bfrag_row) * (PP*2) + bfrag_koff);
            ldsm_x4(bh, b_base + off);
            ldsm_x4(blr, bl_base + off);
            #pragma unroll
            for (int s = 0; s < 2; s++) {
                #pragma unroll
                for (int mi = 0; mi < 2; mi++) {
                    float* cc = acc[mi][g * 2 + s];
                    mma_bf16(cc, ah[mi],  bh[2*s],  bh[2*s+1]);
                    mma_bf16(cc, ah[mi],  blr[2*s], blr[2*s+1]);
                    mma_bf16(cc, alr[mi], bh[2*s],  bh[2*s+1]);
                }
            }
        }
        __syncthreads();
    }

    #pragma unroll
    for (int mi = 0; mi < 2; mi++) {
        #pragma unroll
        for (int ni = 0; ni < 8; ni++) {
            const int row = i0 + wm + mi * 16 + (lane >> 2);
            const int col = n0 + wn + ni * 8 + (lane & 3) * 2;
            float2 bb2 = *(const float2*)(bias + col);
            float v0 = acc[mi][ni][0] + bb2.x, v1 = acc[mi][ni][1] + bb2.y;
            float v2 = acc[mi][ni][2] + bb2.x, v3 = acc[mi][ni][3] + bb2.y;
            if (mode == 1) {
                *(float2*)(out_ext + (size_t)row * Wd + col) = make_float2(v0, v1);
                *(float2*)(out_ext + (size_t)(row + 8) * Wd + col) = make_float2(v2, v3);
            } else {
                ushort h0,l0,h1,l1,h2,l2,h3,l3;
                split_bf(v0,h0,l0); split_bf(v1,h1,l1);
                split_bf(v2,h2,l2); split_bf(v3,h3,l3);
                *(ushort2*)(oh + (size_t)row * Wd + col) = make_ushort2(h0,h1);
                *(ushort2*)(ol + (size_t)row * Wd + col) = make_ushort2(l0,l1);
                *(ushort2*)(oh + (size_t)(row + 8) * Wd + col) = make_ushort2(h2,h3);
                *(ushort2*)(ol + (size_t)(row + 8) * Wd + col) = make_ushort2(l2,l3);
            }
        }
    }
}

// ===========================================================================
// Attention smem geometry (pitch 72 ushorts = 144B)
// ===========================================================================
#define PITCH 72
#define QT    (128*PITCH)
#define KT    (64*PITCH)

__device__ __forceinline__ void prefetch_q(uint32_t sb, const ushort* qh,
                                           const ushort* ql, int t) {
    #pragma unroll
    for (int u = 0; u < 8; u++) {
        const int arr = u >> 2;
        const int rem = ((u & 3) << 8) + t;
        const int row = rem >> 3, ch = rem & 7;
        const ushort* src = (arr == 0 ? qh : ql) + (size_t)row * Wd + ch * 8;
        cp16(sb + (arr * QT + row * PITCH + ch * 8) * 2, src);
    }
    CP_COMMIT();
}

// ===========================================================================
// stats_mma: streaming QK^T -> per-row (max, 1/sum). grid(8,48), 256 thr.
// ===========================================================================
#define STATS_KVB (2*KT)
#define STATS_SMEM ((2*QT + 2*STATS_KVB)*2 + Sq*4)
__global__ __launch_bounds__(256, 2)
void stats_mma(const int* __restrict__ mask) {
    extern __shared__ ushort smem_u[];
    float* MA = (float*)(smem_u + 2*QT + 2*STATS_KVB);

    const int t = threadIdx.x;
    const int wid = t >> 5;
    const int lane = t & 31;
    const int z = blockIdx.y;
    const int b = z / Hh;
    const int h = z - b * Hh;
    const int i0 = blockIdx.x * 128;
    const int wm = wid * 16;

    const size_t qoff = ((size_t)b * Sq + i0) * Wd + h * Dd;
    const size_t koff = (size_t)b * Sq * Wd + h * Dd;

    const uint32_t sb = (uint32_t)__cvta_generic_to_shared(smem_u);

    auto prefetch_k = [&](int jt, int bsel) {
        const uint32_t base = sb + (2*QT + bsel * STATS_KVB) * 2;
        const ushort* kh = g_kh + koff + (size_t)jt * 64 * Wd;
        const ushort* kl = g_kl + koff + (size_t)jt * 64 * Wd;
        #pragma unroll
        for (int u = 0; u < 4; u++) {
            const int arr = u >> 1;
            const int rem = ((u & 1) << 8) + t;
            const int row = rem >> 3, ch = rem & 7;
            const ushort* src = (arr == 0 ? kh : kl) + (size_t)row * Wd + ch * 8;
            cp16(base + (arr * KT + row * PITCH + ch * 8) * 2, src);
        }
        CP_COMMIT();
    };

    prefetch_q(sb, g_qh + qoff, g_ql + qoff, t);
    prefetch_k(0, 0);
    #pragma unroll
    for (int i = t; i < Sq; i += 256)
        MA[i] = __ldg(mask + b * Sq + i) ? 0.f : -1e9f;

    CP_WAIT(1);
    __syncthreads();

    const int frag_row = ((lane >> 3) & 1) * 8 + (lane & 7);
    const int frag_koff = (lane >> 4) * 16;
    const int bfrag_row = ((lane >> 4) & 1) * 8 + (lane & 7);
    const int bfrag_koff = ((lane >> 3) & 1) * 16;

    uint32_t qh[4][4], ql[4][4];
    #pragma unroll
    for (int kb = 0; kb < 4; kb++) {
        const uint32_t off = (uint32_t)((wm + frag_row) * (PITCH * 2) + kb * 32 + frag_koff);
        ldsm_x4(qh[kb], sb + off);
        ldsm_x4(ql[kb], sb + QT * 2 + off);
    }

    float m0 = -3.4e38f, s0 = 0.f, m1 = -3.4e38f, s1 = 0.f;

    for (int jt = 0; jt < 16; jt++) {
        if (jt + 1 < 16) { prefetch_k(jt + 1, (jt + 1) & 1); CP_WAIT(1); }
        else             { CP_WAIT(0); }
        __syncthreads();

        const uint32_t kh_base = sb + (2*QT + (jt & 1) * STATS_KVB) * 2;
        const uint32_t kl_base = kh_base + KT * 2;
        const int j0 = jt * 64;

        #pragma unroll
        for (int p = 0; p < 4; p++) {
            float acc[2][4] = {};
            #pragma unroll
            for (int kb = 0; kb < 4; kb++) {
                uint32_t kh[4], kl[4];
                const uint32_t off = (uint32_t)((p * 16 + bfrag_row) * (PITCH * 2) + kb * 32 + bfrag_koff);
                ldsm_x4(kh, kh_base + off);
                ldsm_x4(kl, kl_base + off);
                #pragma unroll
                for (int s = 0; s < 2; s++) {
                    mma_bf16(acc[s], qh[kb], kh[2*s], kh[2*s+1]);
                    mma_bf16(acc[s], qh[kb], kl[2*s], kl[2*s+1]);
                    mma_bf16(acc[s], ql[kb], kh[2*s], kh[2*s+1]);
                }
            }
            #pragma unroll
            for (int s = 0; s < 2; s++) {
                const int col = j0 + p * 16 + s * 8 + (lane & 3) * 2;
                const float ma0 = MA[col], ma1 = MA[col + 1];
                float v0 = acc[s][0] * 0.125f + ma0;
                float v1 = acc[s][1] * 0.125f + ma1;
                float v2 = acc[s][2] * 0.125f + ma0;
                float v3 = acc[s][3] * 0.125f + ma1;
                float nm0 = fmaxf(m0, fmaxf(v0, v1));
                s0 = s0 * __expf(m0 - nm0) + __expf(v0 - nm0) + __expf(v1 - nm0);
                m0 = nm0;
                float nm1 = fmaxf(m1, fmaxf(v2, v3));
                s1 = s1 * __expf(m1 - nm1) + __expf(v2 - nm1) + __expf(v3 - nm1);
                m1 = nm1;
            }
        }
        __syncthreads();
    }

    #pragma unroll
    for (int off = 1; off < 4; off <<= 1) {
        float mo = __shfl_xor_sync(0xffffffffu, m0, off);
        float so = __shfl_xor_sync(0xffffffffu, s0, off);
        float nm = fmaxf(m0, mo);
        s0 = s0 * __expf(m0 - nm) + so * __expf(mo - nm);
        m0 = nm;
        mo = __shfl_xor_sync(0xffffffffu, m1, off);
        so = __shfl_xor_sync(0xffffffffu, s1, off);
        nm = fmaxf(m1, mo);
        s1 = s1 * __expf(m1 - nm) + so * __expf(mo - nm);
        m1 = nm;
    }
    if ((lane & 3) == 0) {
        const int r = i0 + wm + (lane >> 2);
        g_rm[z * Sq + r] = m0;
        g_ri[z * Sq + r] = 1.0f / s0;
        g_rm[z * Sq + r + 8] = m1;
        g_ri[z * Sq + r + 8] = 1.0f / s1;
    }
}

// ===========================================================================
// av_mma: recompute QK^T, normalize, write P once, fused P@V. cp.async DB.
// ===========================================================================
#define AV_KVB (4*KT)
#define AV_SMEM ((2*QT + 2*AV_KVB)*2 + Sq*4)
__global__ __launch_bounds__(256, 2)
void av_mma(const int* __restrict__ mask, float* __restrict__ attn_out) {
    extern __shared__ ushort smem_u[];
    float* MA = (float*)(smem_u + 2*QT + 2*AV_KVB);

    float* attnW = attn_out ? attn_out : g_attn_fallback;

    const int t = threadIdx.x;
    const int wid = t >> 5;
    const int lane = t & 31;
    const int z = blockIdx.y;
    const int b = z / Hh;
    const int h = z - b * Hh;
    const int i0 = blockIdx.x * 128;
    const int wm = wid * 16;

    const size_t qoff = ((size_t)b * Sq + i0) * Wd + h * Dd;
    const size_t koff = (size_t)b * Sq * Wd + h * Dd;

    const uint32_t sb = (uint32_t)__cvta_generic_to_shared(smem_u);

    auto prefetch_kv = [&](int jt, int bsel) {
        const uint32_t base = sb + (2*QT + bsel * AV_KVB) * 2;
        const size_t off = koff + (size_t)jt * 64 * Wd;
        const ushort* s4[4] = { g_kh + off, g_kl + off, g_vh + off, g_vl + off };
        #pragma unroll
        for (int u = 0; u < 8; u++) {
            const int arr = u >> 1;
            const int rem = ((u & 1) << 8) + t;
            const int row = rem >> 3, ch = rem & 7;
            cp16(base + (arr * KT + row * PITCH + ch * 8) * 2,
                 s4[arr] + (size_t)row * Wd + ch * 8);
        }
        CP_COMMIT();
    };

    prefetch_q(sb, g_qh + qoff, g_ql + qoff, t);
    prefetch_kv(0, 0);
    #pragma unroll
    for (int i = t; i < Sq; i += 256)
        MA[i] = __ldg(mask + b * Sq + i) ? 0.f : -1e9f;

    CP_WAIT(1);
    __syncthreads();

    const int frag_row = ((lane >> 3) & 1) * 8 + (lane & 7);
    const int frag_koff = (lane >> 4) * 16;
    const int bfrag_row = ((lane >> 4) & 1) * 8 + (lane & 7);
    const int bfrag_koff = ((lane >> 3) & 1) * 16;
    const int tfrag_row = ((lane >> 3) & 1) * 8 + (lane & 7);
    const int tfrag_noff = ((lane >> 4) & 1) * 16;

    uint32_t qh[4][4], ql[4][4];
    #pragma unroll
    for (int kb = 0; kb < 4; kb++) {
        const uint32_t off = (uint32_t)((wm + frag_row) * (PITCH * 2) + kb * 32 + frag_koff);
        ldsm_x4(qh[kb], sb + off);
        ldsm_x4(ql[kb], sb + QT * 2 + off);
    }

    const int r0 = wm + (lane >> 2);
    const float mm0 = g_rm[z * Sq + i0 + r0];
    const float ii0 = g_ri[z * Sq + i0 + r0];
    const float mm1 = g_rm[z * Sq + i0 + r0 + 8];
    const float ii1 = g_ri[z * Sq + i0 + r0 + 8];

    float ctx[8][4];
    #pragma unroll
    for (int ni = 0; ni < 8; ni++)
        #pragma unroll
        for (int j = 0; j < 4; j++) ctx[ni][j] = 0.f;

    float* Prow0 = attnW + ((size_t)z * Sq + i0 + r0) * Sq;
    float* Prow1 = attnW + ((size_t)z * Sq + i0 + r0 + 8) * Sq;

    for (int jt = 0; jt < 16; jt++) {
        if (jt + 1 < 16) { prefetch_kv(jt + 1, (jt + 1) & 1); CP_WAIT(1); }
        else             { CP_WAIT(0); }
        __syncthreads();

        const uint32_t kb0 = sb + (2*QT + (jt & 1) * AV_KVB) * 2;
        const uint32_t kh_base = kb0;
        const uint32_t kl_base = kb0 + KT * 2;
        const uint32_t vh_base = kb0 + 2 * KT * 2;
        const uint32_t vl_base = kb0 + 3 * KT * 2;
        const int j0 = jt * 64;

        #pragma unroll
        for (int p = 0; p < 4; p++) {
            float acc[2][4] = {};
            #pragma unroll
            for (int kb = 0; kb < 4; kb++) {
                uint32_t kh[4], kl[4];
                const uint32_t off = (uint32_t)((p * 16 + bfrag_row) * (PITCH * 2) + kb * 32 + bfrag_koff);
                ldsm_x4(kh, kh_base + off);
                ldsm_x4(kl, kl_base + off);
                #pragma unroll
                for (int s = 0; s < 2; s++) {
                    mma_bf16(acc[s], qh[kb], kh[2*s], kh[2*s+1]);
                    mma_bf16(acc[s], qh[kb], kl[2*s], kl[2*s+1]);
                    mma_bf16(acc[s], ql[kb], kh[2*s], kh[2*s+1]);
                }
            }
            uint32_t pfh[4], pfl[4];
            #pragma unroll
            for (int s = 0; s < 2; s++) {
                const int col = j0 + p * 16 + s * 8 + (lane & 3) * 2;
                const float ma0 = MA[col], ma1 = MA[col + 1];
                float v0 = acc[s][0] * 0.125f + ma0;
                float v1 = acc[s][1] * 0.125f + ma1;
                float v2 = acc[s][2] * 0.125f + ma0;
                float v3 = acc[s][3] * 0.125f + ma1;
                float p0 = __expf(v0 - mm0) * ii0;
                float p1 = __expf(v1 - mm0) * ii0;
                float p2 = __expf(v2 - mm1) * ii1;
                float p3 = __expf(v3 - mm1) * ii1;
                *(float2*)(Prow0 + col) = make_float2(p0, p1);
                *(float2*)(Prow1 + col) = make_float2(p2, p3);
                ushort h0,l0,h1,l1,h2,l2,h3,l3;
                split_bf(p0,h0,l0); split_bf(p1,h1,l1);
                split_bf(p2,h2,l2); split_bf(p3,h3,l3);
                pfh[s*2+0] = (uint32_t)h0 | ((uint32_t)h1 << 16);
                pfh[s*2+1] = (uint32_t)h2 | ((uint32_t)h3 << 16);
                pfl[s*2+0] = (uint32_t)l0 | ((uint32_t)l1 << 16);
                pfl[s*2+1] = (uint32_t)l2 | ((uint32_t)l3 << 16);
            }
            #pragma unroll
            for (int gv = 0; gv < 4; gv++) {
                uint32_t vh[4], vl[4];
                const uint32_t off = (uint32_t)((p * 16 + tfrag_row) * (PITCH * 2) + gv * 32 + tfrag_noff);
                ldsm_x4_t(vh, vh_base + off);
                ldsm_x4_t(vl, vl_base + off);
                #pragma unroll
                for (int s = 0; s < 2; s++) {
                    float* cc = ctx[gv * 2 + s];
                    mma_bf16(cc, pfh, vh[2*s], vh[2*s+1]);
                    mma_bf16(cc, pfh, vl[2*s], vl[2*s+1]);
                    mma_bf16(cc, pfl, vh[2*s], vh[2*s+1]);
                }
            }
        }
        __syncthreads();
    }

    #pragma unroll
    for (int ni = 0; ni < 8; ni++) {
        const int col = (ni >> 1) * 16 + (ni & 1) * 8 + (lane & 3) * 2;
        const size_t o0 = ((size_t)b * Sq + i0 + r0) * Wd + h * Dd + col;
        const size_t o1 = ((size_t)b * Sq + i0 + r0 + 8) * Wd + h * Dd + col;
        ushort h0,l0,h1,l1,h2,l2,h3,l3;
        split_bf(ctx[ni][0],h0,l0); split_bf(ctx[ni][1],h1,l1);
        split_bf(ctx[ni][2],h2,l2); split_bf(ctx[ni][3],h3,l3);
        *(ushort2*)(g_ch + o0) = make_ushort2(h0,h1);
        *(ushort2*)(g_cl + o0) = make_ushort2(l0,l1);
        *(ushort2*)(g_ch + o1) = make_ushort2(h2,h3);
        *(ushort2*)(g_cl + o1) = make_ushort2(l2,l3);
    }
}

// ---------------------------------------------------------------------------
extern "C" void kernel_launch(void* const* d_in, const int* in_sizes, int n_in,
                              void* d_out, int out_size) {
    const float* query = (const float*)d_in[0];
    const int*   mask  = (const int*)d_in[1];
    const float* q_w = (const float*)d_in[2];
    const float* q_b = (const float*)d_in[3];
    const float* k_w = (const float*)d_in[4];
    const float* k_b = (const float*)d_in[5];
    const float* v_w = (const float*)d_in[6];
    const float* v_b = (const float*)d_in[7];
    const float* o_w = (const float*)d_in[8];
    const float* o_b = (const float*)d_in[9];

    float* out = (float*)d_out;
    float* attn = ((long long)out_size >= OUT_ELEMS + ATTN_ELEMS) ? out + OUT_ELEMS : nullptr;

    cudaFuncSetAttribute(proj_mma, cudaFuncAttributeMaxDynamicSharedMemorySize, PROJ_SMEM);
    cudaFuncSetAttribute(stats_mma, cudaFuncAttributeMaxDynamicSharedMemorySize, STATS_SMEM);
    cudaFuncSetAttribute(av_mma, cudaFuncAttributeMaxDynamicSharedMemorySize, AV_SMEM);
    cudaFuncSetAttribute(av_mma, cudaFuncAttributePreferredSharedMemoryCarveout, 100);
    cudaFuncSetAttribute(stats_mma, cudaFuncAttributePreferredSharedMemoryCarveout, 100);

    const int conv_blocks = (BSq * (Wd / 2) + 255) / 256;
    conv_kernel<<<dim3(conv_blocks, 5), 256>>>(query, q_w, k_w, v_w, o_w);
    proj_mma<<<dim3(6, 32, 3), 256, PROJ_SMEM>>>(0, q_b, k_b, v_b, nullptr);
    stats_mma<<<dim3(8, NZ), 256, STATS_SMEM>>>(mask);
    av_mma<<<dim3(8, NZ), 256, AV_SMEM>>>(mask, attn);
    proj_mma<<<dim3(6, 32, 1), 256, PROJ_SMEM>>>(1, o_b, nullptr, nullptr, out);
}

// round 11
// speedup vs baseline: 1.3237x; 1.0470x over previous
#include <cuda_runtime.h>
#include <cuda_bf16.h>
#include <cstdint>

// Fixed shapes: B=4, S=1024, E=1024, width=768 -> H=12, D=64
#define Bq   4
#define Sq   1024
#define Eq   1024
#define Wd   768
#define Hh   12
#define Dd   64
#define BSq  (Bq*Sq)
#define NZ   (Bq*Hh)
#define WW   (Wd*Wd)
#define OUT_ELEMS   ((long long)BSq*Wd)
#define ATTN_ELEMS  ((long long)NZ*Sq*Sq)

// ---------------- scratch (device globals; no runtime allocation) ----------
__device__ __align__(16) ushort g_xh[BSq*Wd], g_xl[BSq*Wd];
__device__ __align__(16) ushort g_wh[4*WW],  g_wl[4*WW];
__device__ __align__(16) ushort g_qh[BSq*Wd], g_ql[BSq*Wd];
__device__ __align__(16) ushort g_kh[BSq*Wd], g_kl[BSq*Wd];
__device__ __align__(16) ushort g_vh[BSq*Wd], g_vl[BSq*Wd];
__device__ __align__(16) ushort g_ch[BSq*Wd], g_cl[BSq*Wd];
__device__ __align__(16) float g_attn_fallback[NZ*Sq*Sq];

// ======================= primitives ========================================
__device__ __forceinline__ void ldsm_x4(uint32_t* r, uint32_t addr) {
    asm volatile("ldmatrix.sync.aligned.m8n8.x4.shared.b16 {%0,%1,%2,%3}, [%4];"
        : "=r"(r[0]), "=r"(r[1]), "=r"(r[2]), "=r"(r[3]) : "r"(addr));
}
__device__ __forceinline__ void ldsm_x4_t(uint32_t* r, uint32_t addr) {
    asm volatile("ldmatrix.sync.aligned.m8n8.x4.trans.shared.b16 {%0,%1,%2,%3}, [%4];"
        : "=r"(r[0]), "=r"(r[1]), "=r"(r[2]), "=r"(r[3]) : "r"(addr));
}
__device__ __forceinline__ void mma_bf16(float* c, const uint32_t* a,
                                         uint32_t b0, uint32_t b1) {
    asm volatile("mma.sync.aligned.m16n8k16.row.col.f32.bf16.bf16.f32 "
        "{%0,%1,%2,%3}, {%4,%5,%6,%7}, {%8,%9}, {%0,%1,%2,%3};"
        : "+f"(c[0]), "+f"(c[1]), "+f"(c[2]), "+f"(c[3])
        : "r"(a[0]), "r"(a[1]), "r"(a[2]), "r"(a[3]), "r"(b0), "r"(b1));
}
__device__ __forceinline__ void split_bf(float v, ushort& h, ushort& l) {
    __nv_bfloat16 hh = __float2bfloat16(v);
    h = __bfloat16_as_ushort(hh);
    l = __bfloat16_as_ushort(__float2bfloat16(v - __bfloat162float(hh)));
}
__device__ __forceinline__ void cp16(uint32_t dst, const void* src) {
    asm volatile("cp.async.cg.shared.global [%0], [%1], 16;" :: "r"(dst), "l"(src));
}
#define CP_COMMIT() asm volatile("cp.async.commit_group;" ::: "memory")
#define CP_WAIT(n)  asm volatile("cp.async.wait_group %0;" :: "n"(n) : "memory")

// ===========================================================================
// conv_kernel: fp32 (stride 1024) -> bf16 hi/lo (stride 768), once.
// ===========================================================================
__global__ __launch_bounds__(256)
void conv_kernel(const float* __restrict__ x,
                 const float* __restrict__ qw, const float* __restrict__ kw,
                 const float* __restrict__ vw, const float* __restrict__ ow) {
    const int z = blockIdx.y;
    const float* src; ushort* dh; ushort* dl; int rows;
    if (z == 0)      { src = x;  dh = g_xh;        dl = g_xl;        rows = BSq; }
    else if (z == 1) { src = qw; dh = g_wh;        dl = g_wl;        rows = Wd; }
    else if (z == 2) { src = kw; dh = g_wh + WW;   dl = g_wl + WW;   rows = Wd; }
    else if (z == 3) { src = vw; dh = g_wh + 2*WW; dl = g_wl + 2*WW; rows = Wd; }
    else             { src = ow; dh = g_wh + 3*WW; dl = g_wl + 3*WW; rows = Wd; }

    const int idx = blockIdx.x * 256 + threadIdx.x;
    const int total = rows * (Wd / 2);
    if (idx >= total) return;
    const int row = idx / (Wd / 2);
    const int c2 = (idx - row * (Wd / 2)) * 2;
    float2 v = *(const float2*)(src + (size_t)row * Eq + c2);
    ushort h0, l0, h1, l1;
    split_bf(v.x, h0, l0);
    split_bf(v.y, h1, l1);
    *(ushort2*)(dh + (size_t)row * Wd + c2) = make_ushort2(h0, h1);
    *(ushort2*)(dl + (size_t)row * Wd + c2) = make_ushort2(l0, l1);
}

// ===========================================================================
// proj_mma: bf16x3 HMMA GEMM with cp.async double-buffered K chunks.
// ===========================================================================
#define PP 24
#define PROJ_TILE (128*PP)
#define PROJ_BUF  (4*PROJ_TILE)
#define PROJ_SMEM (2*PROJ_BUF*2)

__global__ __launch_bounds__(256, 2)
void proj_mma(int mode, const float* __restrict__ b0, const float* __restrict__ b1,
              const float* __restrict__ b2, float* __restrict__ out_ext) {
    extern __shared__ ushort psm[];

    const int t = threadIdx.x;
    const int wid = t >> 5;
    const int lane = t & 31;

    const ushort *Axh, *Axl, *Wxh, *Wxl;
    const float* bias;
    ushort *oh = nullptr, *ol = nullptr;
    if (mode == 1) {
        Axh = g_ch; Axl = g_cl;
        Wxh = g_wh + 3*WW; Wxl = g_wl + 3*WW;
        bias = b0;
    } else {
        Axh = g_xh; Axl = g_xl;
        const int z = blockIdx.z;
        Wxh = g_wh + z*WW; Wxl = g_wl + z*WW;
        bias = (z == 0) ? b0 : (z == 1) ? b1 : b2;
        if (z == 0)      { oh = g_qh; ol = g_ql; }
        else if (z == 1) { oh = g_kh; ol = g_kl; }
        else             { oh = g_vh; ol = g_vl; }
    }

    const int n0 = blockIdx.x * 128;
    const int i0 = blockIdx.y * 128;
    const int wm = (wid & 3) * 32;
    const int wn = (wid >> 2) * 64;

    const uint32_t sb = (uint32_t)__cvta_generic_to_shared(psm);
    const int prow = t >> 1;
    const int pch = t & 1;

    const ushort* s4[4] = { Axh + (size_t)(i0 + prow) * Wd,
                            Axl + (size_t)(i0 + prow) * Wd,
                            Wxh + (size_t)(n0 + prow) * Wd,
                            Wxl + (size_t)(n0 + prow) * Wd };

    auto prefetch = [&](int c, int bsel) {
        const uint32_t base = sb + bsel * (PROJ_BUF * 2) + (prow * PP + pch * 8) * 2;
        const int k0 = c * 16;
        #pragma unroll
        for (int u = 0; u < 4; u++)
            cp16(base + u * (PROJ_TILE * 2), s4[u] + k0 + pch * 8);
        CP_COMMIT();
    };

    float acc[2][8][4];
    #pragma unroll
    for (int mi = 0; mi < 2; mi++)
        #pragma unroll
        for (int ni = 0; ni < 8; ni++)
            #pragma unroll
            for (int j = 0; j < 4; j++) acc[mi][ni][j] = 0.f;

    const int frag_row = ((lane >> 3) & 1) * 8 + (lane & 7);
    const int frag_koff = (lane >> 4) * 16;
    const int bfrag_row = ((lane >> 4) & 1) * 8 + (lane & 7);
    const int bfrag_koff = ((lane >> 3) & 1) * 16;

    prefetch(0, 0);

    for (int c = 0; c < 48; c++) {
        if (c + 1 < 48) { prefetch(c + 1, (c + 1) & 1); CP_WAIT(1); }
        else            { CP_WAIT(0); }
        __syncthreads();

        const uint32_t bb = sb + (c & 1) * (PROJ_BUF * 2);
        const uint32_t a_base = bb;
        const uint32_t al_base = bb + PROJ_TILE * 2;
        const uint32_t b_base = bb + 2 * PROJ_TILE * 2;
        const uint32_t bl_base = bb + 3 * PROJ_TILE * 2;

        uint32_t ah[2][4], alr[2][4];
        #pragma unroll
        for (int mi = 0; mi < 2; mi++) {
            const uint32_t off = (uint32_t)((wm + mi * 16 + frag_row) * (PP*2) + frag_koff);
            ldsm_x4(ah[mi], a_base + off);
            ldsm_x4(alr[mi], al_base + off);
        }
        #pragma unroll
        for (int g = 0; g < 4; g++) {
            uint32_t bh[4], blr[4];
            const uint32_t off = (uint32_t)((wn + g * 16 + bfrag_row) * (PP*2) + bfrag_koff);
            ldsm_x4(bh, b_base + off);
            ldsm_x4(blr, bl_base + off);
            #pragma unroll
            for (int s = 0; s < 2; s++) {
                #pragma unroll
                for (int mi = 0; mi < 2; mi++) {
                    float* cc = acc[mi][g * 2 + s];
                    mma_bf16(cc, ah[mi],  bh[2*s],  bh[2*s+1]);
                    mma_bf16(cc, ah[mi],  blr[2*s], blr[2*s+1]);
                    mma_bf16(cc, alr[mi], bh[2*s],  bh[2*s+1]);
                }
            }
        }
        __syncthreads();
    }

    #pragma unroll
    for (int mi = 0; mi < 2; mi++) {
        #pragma unroll
        for (int ni = 0; ni < 8; ni++) {
            const int row = i0 + wm + mi * 16 + (lane >> 2);
            const int col = n0 + wn + ni * 8 + (lane & 3) * 2;
            float2 bb2 = *(const float2*)(bias + col);
            float v0 = acc[mi][ni][0] + bb2.x, v1 = acc[mi][ni][1] + bb2.y;
            float v2 = acc[mi][ni][2] + bb2.x, v3 = acc[mi][ni][3] + bb2.y;
            if (mode == 1) {
                *(float2*)(out_ext + (size_t)row * Wd + col) = make_float2(v0, v1);
                *(float2*)(out_ext + (size_t)(row + 8) * Wd + col) = make_float2(v2, v3);
            } else {
                ushort h0,l0,h1,l1,h2,l2,h3,l3;
                split_bf(v0,h0,l0); split_bf(v1,h1,l1);
                split_bf(v2,h2,l2); split_bf(v3,h3,l3);
                *(ushort2*)(oh + (size_t)row * Wd + col) = make_ushort2(h0,h1);
                *(ushort2*)(ol + (size_t)row * Wd + col) = make_ushort2(l0,l1);
                *(ushort2*)(oh + (size_t)(row + 8) * Wd + col) = make_ushort2(h2,h3);
                *(ushort2*)(ol + (size_t)(row + 8) * Wd + col) = make_ushort2(l2,l3);
            }
        }
    }
}

// ===========================================================================
// Attention smem geometry (pitch 72 ushorts = 144B)
// ===========================================================================
#define PITCH 72
#define QT    (128*PITCH)
#define KT    (64*PITCH)

__device__ __forceinline__ void prefetch_q(uint32_t sb, const ushort* qh,
                                           const ushort* ql, int t) {
    #pragma unroll
    for (int u = 0; u < 8; u++) {
        const int arr = u >> 2;
        const int rem = ((u & 3) << 8) + t;
        const int row = rem >> 3, ch = rem & 7;
        const ushort* src = (arr == 0 ? qh : ql) + (size_t)row * Wd + ch * 8;
        cp16(sb + (arr * QT + row * PITCH + ch * 8) * 2, src);
    }
    CP_COMMIT();
}

// ===========================================================================
// attn_mma: FUSED two-pass fixed-base-softmax flash attention.
// Pass A: stream K, QK^T (bf16x3), row sums of exp (base 0) -> registers.
// Pass B: stream K+V, recompute QK^T, write P = exp(v)/S once, fused P@V.
// grid(8, 48), 256 threads, 2 CTAs/SM.
// ===========================================================================
#define AV_KVB (4*KT)
#define AV_SMEM ((2*QT + 2*AV_KVB)*2 + Sq*4)
__global__ __launch_bounds__(256, 2)
void attn_mma(const int* __restrict__ mask, float* __restrict__ attn_out) {
    extern __shared__ ushort smem_u[];
    float* MA = (float*)(smem_u + 2*QT + 2*AV_KVB);

    float* attnW = attn_out ? attn_out : g_attn_fallback;

    const int t = threadIdx.x;
    const int wid = t >> 5;
    const int lane = t & 31;
    const int z = blockIdx.y;
    const int b = z / Hh;
    const int h = z - b * Hh;
    const int i0 = blockIdx.x * 128;
    const int wm = wid * 16;

    const size_t qoff = ((size_t)b * Sq + i0) * Wd + h * Dd;
    const size_t koff = (size_t)b * Sq * Wd + h * Dd;

    const uint32_t sb = (uint32_t)__cvta_generic_to_shared(smem_u);

    // K-only prefetch into the same buffer layout (kh at 0, kl at KT)
    auto prefetch_k = [&](int jt, int bsel) {
        const uint32_t base = sb + (2*QT + bsel * AV_KVB) * 2;
        const size_t off = koff + (size_t)jt * 64 * Wd;
        const ushort* s2[2] = { g_kh + off, g_kl + off };
        #pragma unroll
        for (int u = 0; u < 4; u++) {
            const int arr = u >> 1;
            const int rem = ((u & 1) << 8) + t;
            const int row = rem >> 3, ch = rem & 7;
            cp16(base + (arr * KT + row * PITCH + ch * 8) * 2,
                 s2[arr] + (size_t)row * Wd + ch * 8);
        }
        CP_COMMIT();
    };
    auto prefetch_kv = [&](int jt, int bsel) {
        const uint32_t base = sb + (2*QT + bsel * AV_KVB) * 2;
        const size_t off = koff + (size_t)jt * 64 * Wd;
        const ushort* s4[4] = { g_kh + off, g_kl + off, g_vh + off, g_vl + off };
        #pragma unroll
        for (int u = 0; u < 8; u++) {
            const int arr = u >> 1;
            const int rem = ((u & 1) << 8) + t;
            const int row = rem >> 3, ch = rem & 7;
            cp16(base + (arr * KT + row * PITCH + ch * 8) * 2,
                 s4[arr] + (size_t)row * Wd + ch * 8);
        }
        CP_COMMIT();
    };

    prefetch_q(sb, g_qh + qoff, g_ql + qoff, t);
    prefetch_k(0, 0);
    #pragma unroll
    for (int i = t; i < Sq; i += 256)
        MA[i] = __ldg(mask + b * Sq + i) ? 0.f : -1e9f;

    CP_WAIT(1);
    __syncthreads();

    const int frag_row = ((lane >> 3) & 1) * 8 + (lane & 7);
    const int frag_koff = (lane >> 4) * 16;
    const int bfrag_row = ((lane >> 4) & 1) * 8 + (lane & 7);
    const int bfrag_koff = ((lane >> 3) & 1) * 16;
    const int tfrag_row = ((lane >> 3) & 1) * 8 + (lane & 7);
    const int tfrag_noff = ((lane >> 4) & 1) * 16;

    uint32_t qh[4][4], ql[4][4];
    #pragma unroll
    for (int kb = 0; kb < 4; kb++) {
        const uint32_t off = (uint32_t)((wm + frag_row) * (PITCH * 2) + kb * 32 + frag_koff);
        ldsm_x4(qh[kb], sb + off);
        ldsm_x4(ql[kb], sb + QT * 2 + off);
    }

    // -------------------- Pass A: row sums of exp(score) --------------------
    float s0 = 0.f, s1 = 0.f;
    for (int jt = 0; jt < 16; jt++) {
        if (jt + 1 < 16) { prefetch_k(jt + 1, (jt + 1) & 1); CP_WAIT(1); }
        else             { CP_WAIT(0); }
        __syncthreads();

        const uint32_t kh_base = sb + (2*QT + (jt & 1) * AV_KVB) * 2;
        const uint32_t kl_base = kh_base + KT * 2;
        const int j0 = jt * 64;

        #pragma unroll
        for (int p = 0; p < 4; p++) {
            float acc[2][4] = {};
            #pragma unroll
            for (int kb = 0; kb < 4; kb++) {
                uint32_t kh[4], kl[4];
                const uint32_t off = (uint32_t)((p * 16 + bfrag_row) * (PITCH * 2) + kb * 32 + bfrag_koff);
                ldsm_x4(kh, kh_base + off);
                ldsm_x4(kl, kl_base + off);
                #pragma unroll
                for (int s = 0; s < 2; s++) {
                    mma_bf16(acc[s], qh[kb], kh[2*s], kh[2*s+1]);
                    mma_bf16(acc[s], qh[kb], kl[2*s], kl[2*s+1]);
                    mma_bf16(acc[s], ql[kb], kh[2*s], kh[2*s+1]);
                }
            }
            #pragma unroll
            for (int s = 0; s < 2; s++) {
                const int col = j0 + p * 16 + s * 8 + (lane & 3) * 2;
                const float ma0 = MA[col], ma1 = MA[col + 1];
                s0 += __expf(acc[s][0] * 0.125f + ma0) + __expf(acc[s][1] * 0.125f + ma1);
                s1 += __expf(acc[s][2] * 0.125f + ma0) + __expf(acc[s][3] * 0.125f + ma1);
            }
        }
        __syncthreads();
    }
    // combine across the 4 lanes of each row quad
    s0 += __shfl_xor_sync(0xffffffffu, s0, 1);
    s0 += __shfl_xor_sync(0xffffffffu, s0, 2);
    s1 += __shfl_xor_sync(0xffffffffu, s1, 1);
    s1 += __shfl_xor_sync(0xffffffffu, s1, 2);
    const float ii0 = 1.0f / s0;
    const float ii1 = 1.0f / s1;

    // -------------------- Pass B: write P, fused P@V ------------------------
    const int r0 = wm + (lane >> 2);
    float ctx[8][4];
    #pragma unroll
    for (int ni = 0; ni < 8; ni++)
        #pragma unroll
        for (int j = 0; j < 4; j++) ctx[ni][j] = 0.f;

    float* Prow0 = attnW + ((size_t)z * Sq + i0 + r0) * Sq;
    float* Prow1 = attnW + ((size_t)z * Sq + i0 + r0 + 8) * Sq;

    prefetch_kv(0, 0);

    for (int jt = 0; jt < 16; jt++) {
        if (jt + 1 < 16) { prefetch_kv(jt + 1, (jt + 1) & 1); CP_WAIT(1); }
        else             { CP_WAIT(0); }
        __syncthreads();

        const uint32_t kb0 = sb + (2*QT + (jt & 1) * AV_KVB) * 2;
        const uint32_t kh_base = kb0;
        const uint32_t kl_base = kb0 + KT * 2;
        const uint32_t vh_base = kb0 + 2 * KT * 2;
        const uint32_t vl_base = kb0 + 3 * KT * 2;
        const int j0 = jt * 64;

        #pragma unroll
        for (int p = 0; p < 4; p++) {
            float acc[2][4] = {};
            #pragma unroll
            for (int kb = 0; kb < 4; kb++) {
                uint32_t kh[4], kl[4];
                const uint32_t off = (uint32_t)((p * 16 + bfrag_row) * (PITCH * 2) + kb * 32 + bfrag_koff);
                ldsm_x4(kh, kh_base + off);
                ldsm_x4(kl, kl_base + off);
                #pragma unroll
                for (int s = 0; s < 2; s++) {
                    mma_bf16(acc[s], qh[kb], kh[2*s], kh[2*s+1]);
                    mma_bf16(acc[s], qh[kb], kl[2*s], kl[2*s+1]);
                    mma_bf16(acc[s], ql[kb], kh[2*s], kh[2*s+1]);
                }
            }
            uint32_t pfh[4], pfl[4];
            #pragma unroll
            for (int s = 0; s < 2; s++) {
                const int col = j0 + p * 16 + s * 8 + (lane & 3) * 2;
                const float ma0 = MA[col], ma1 = MA[col + 1];
                float p0 = __expf(acc[s][0] * 0.125f + ma0) * ii0;
                float p1 = __expf(acc[s][1] * 0.125f + ma1) * ii0;
                float p2 = __expf(acc[s][2] * 0.125f + ma0) * ii1;
                float p3 = __expf(acc[s][3] * 0.125f + ma1) * ii1;
                *(float2*)(Prow0 + col) = make_float2(p0, p1);
                *(float2*)(Prow1 + col) = make_float2(p2, p3);
                ushort h0,l0,h1,l1,h2,l2,h3,l3;
                split_bf(p0,h0,l0); split_bf(p1,h1,l1);
                split_bf(p2,h2,l2); split_bf(p3,h3,l3);
                pfh[s*2+0] = (uint32_t)h0 | ((uint32_t)h1 << 16);
                pfh[s*2+1] = (uint32_t)h2 | ((uint32_t)h3 << 16);
                pfl[s*2+0] = (uint32_t)l0 | ((uint32_t)l1 << 16);
                pfl[s*2+1] = (uint32_t)l2 | ((uint32_t)l3 << 16);
            }
            #pragma unroll
            for (int gv = 0; gv < 4; gv++) {
                uint32_t vh[4], vl[4];
                const uint32_t off = (uint32_t)((p * 16 + tfrag_row) * (PITCH * 2) + gv * 32 + tfrag_noff);
                ldsm_x4_t(vh, vh_base + off);
                ldsm_x4_t(vl, vl_base + off);
                #pragma unroll
                for (int s = 0; s < 2; s++) {
                    float* cc = ctx[gv * 2 + s];
                    mma_bf16(cc, pfh, vh[2*s], vh[2*s+1]);
                    mma_bf16(cc, pfh, vl[2*s], vl[2*s+1]);
                    mma_bf16(cc, pfl, vh[2*s], vh[2*s+1]);
                }
            }
        }
        __syncthreads();
    }

    #pragma unroll
    for (int ni = 0; ni < 8; ni++) {
        const int col = (ni >> 1) * 16 + (ni & 1) * 8 + (lane & 3) * 2;
        const size_t o0 = ((size_t)b * Sq + i0 + r0) * Wd + h * Dd + col;
        const size_t o1 = ((size_t)b * Sq + i0 + r0 + 8) * Wd + h * Dd + col;
        ushort h0,l0,h1,l1,h2,l2,h3,l3;
        split_bf(ctx[ni][0],h0,l0); split_bf(ctx[ni][1],h1,l1);
        split_bf(ctx[ni][2],h2,l2); split_bf(ctx[ni][3],h3,l3);
        *(ushort2*)(g_ch + o0) = make_ushort2(h0,h1);
        *(ushort2*)(g_cl + o0) = make_ushort2(l0,l1);
        *(ushort2*)(g_ch + o1) = make_ushort2(h2,h3);
        *(ushort2*)(g_cl + o1) = make_ushort2(l2,l3);
    }
}

// ---------------------------------------------------------------------------
extern "C" void kernel_launch(void* const* d_in, const int* in_sizes, int n_in,
                              void* d_out, int out_size) {
    const float* query = (const float*)d_in[0];
    const int*   mask  = (const int*)d_in[1];
    const float* q_w = (const float*)d_in[2];
    const float* q_b = (const float*)d_in[3];
    const float* k_w = (const float*)d_in[4];
    const float* k_b = (const float*)d_in[5];
    const float* v_w = (const float*)d_in[6];
    const float* v_b = (const float*)d_in[7];
    const float* o_w = (const float*)d_in[8];
    const float* o_b = (const float*)d_in[9];

    float* out = (float*)d_out;
    float* attn = ((long long)out_size >= OUT_ELEMS + ATTN_ELEMS) ? out + OUT_ELEMS : nullptr;

    cudaFuncSetAttribute(proj_mma, cudaFuncAttributeMaxDynamicSharedMemorySize, PROJ_SMEM);
    cudaFuncSetAttribute(attn_mma, cudaFuncAttributeMaxDynamicSharedMemorySize, AV_SMEM);
    cudaFuncSetAttribute(attn_mma, cudaFuncAttributePreferredSharedMemoryCarveout, 100);

    const int conv_blocks = (BSq * (Wd / 2) + 255) / 256;
    conv_kernel<<<dim3(conv_blocks, 5), 256>>>(query, q_w, k_w, v_w, o_w);
    proj_mma<<<dim3(6, 32, 3), 256, PROJ_SMEM>>>(0, q_b, k_b, v_b, nullptr);
    attn_mma<<<dim3(8, NZ), 256, AV_SMEM>>>(mask, attn);
    proj_mma<<<dim3(6, 32, 1), 256, PROJ_SMEM>>>(1, o_b, nullptr, nullptr, out);
}

// round 12
// speedup vs baseline: 1.4536x; 1.0981x over previous
#include <cuda_runtime.h>
#include <cuda_bf16.h>
#include <cstdint>

// Fixed shapes: B=4, S=1024, E=1024, width=768 -> H=12, D=64
#define Bq   4
#define Sq   1024
#define Eq   1024
#define Wd   768
#define Hh   12
#define Dd   64
#define BSq  (Bq*Sq)
#define NZ   (Bq*Hh)
#define WW   (Wd*Wd)
#define OUT_ELEMS   ((long long)BSq*Wd)
#define ATTN_ELEMS  ((long long)NZ*Sq*Sq)

// ---------------- scratch (device globals; no runtime allocation) ----------
__device__ __align__(16) ushort g_xh[BSq*Wd], g_xl[BSq*Wd];
__device__ __align__(16) ushort g_wh[4*WW],  g_wl[4*WW];
__device__ __align__(16) ushort g_qh[BSq*Wd], g_ql[BSq*Wd];
__device__ __align__(16) ushort g_kh[BSq*Wd], g_kl[BSq*Wd];
__device__ __align__(16) ushort g_vh[BSq*Wd], g_vl[BSq*Wd];
__device__ __align__(16) ushort g_ch[BSq*Wd], g_cl[BSq*Wd];
__device__ __align__(16) float g_attn_fallback[NZ*Sq*Sq];

// ======================= primitives ========================================
__device__ __forceinline__ void ldsm_x4(uint32_t* r, uint32_t addr) {
    asm volatile("ldmatrix.sync.aligned.m8n8.x4.shared.b16 {%0,%1,%2,%3}, [%4];"
        : "=r"(r[0]), "=r"(r[1]), "=r"(r[2]), "=r"(r[3]) : "r"(addr));
}
__device__ __forceinline__ void ldsm_x4_t(uint32_t* r, uint32_t addr) {
    asm volatile("ldmatrix.sync.aligned.m8n8.x4.trans.shared.b16 {%0,%1,%2,%3}, [%4];"
        : "=r"(r[0]), "=r"(r[1]), "=r"(r[2]), "=r"(r[3]) : "r"(addr));
}
__device__ __forceinline__ void mma_bf16(float* c, const uint32_t* a,
                                         uint32_t b0, uint32_t b1) {
    asm volatile("mma.sync.aligned.m16n8k16.row.col.f32.bf16.bf16.f32 "
        "{%0,%1,%2,%3}, {%4,%5,%6,%7}, {%8,%9}, {%0,%1,%2,%3};"
        : "+f"(c[0]), "+f"(c[1]), "+f"(c[2]), "+f"(c[3])
        : "r"(a[0]), "r"(a[1]), "r"(a[2]), "r"(a[3]), "r"(b0), "r"(b1));
}
__device__ __forceinline__ void split_bf(float v, ushort& h, ushort& l) {
    __nv_bfloat16 hh = __float2bfloat16(v);
    h = __bfloat16_as_ushort(hh);
    l = __bfloat16_as_ushort(__float2bfloat16(v - __bfloat162float(hh)));
}
__device__ __forceinline__ void cp16(uint32_t dst, const void* src) {
    asm volatile("cp.async.cg.shared.global [%0], [%1], 16;" :: "r"(dst), "l"(src));
}
#define CP_COMMIT() asm volatile("cp.async.commit_group;" ::: "memory")
#define CP_WAIT(n)  asm volatile("cp.async.wait_group %0;" :: "n"(n) : "memory")

// ===========================================================================
// conv_kernel: fp32 (stride 1024) -> bf16 hi/lo (stride 768), once.
// ===========================================================================
__global__ __launch_bounds__(256)
void conv_kernel(const float* __restrict__ x,
                 const float* __restrict__ qw, const float* __restrict__ kw,
                 const float* __restrict__ vw, const float* __restrict__ ow) {
    const int z = blockIdx.y;
    const float* src; ushort* dh; ushort* dl; int rows;
    if (z == 0)      { src = x;  dh = g_xh;        dl = g_xl;        rows = BSq; }
    else if (z == 1) { src = qw; dh = g_wh;        dl = g_wl;        rows = Wd; }
    else if (z == 2) { src = kw; dh = g_wh + WW;   dl = g_wl + WW;   rows = Wd; }
    else if (z == 3) { src = vw; dh = g_wh + 2*WW; dl = g_wl + 2*WW; rows = Wd; }
    else             { src = ow; dh = g_wh + 3*WW; dl = g_wl + 3*WW; rows = Wd; }

    const int idx = blockIdx.x * 256 + threadIdx.x;
    const int total = rows * (Wd / 2);
    if (idx >= total) return;
    const int row = idx / (Wd / 2);
    const int c2 = (idx - row * (Wd / 2)) * 2;
    float2 v = *(const float2*)(src + (size_t)row * Eq + c2);
    ushort h0, l0, h1, l1;
    split_bf(v.x, h0, l0);
    split_bf(v.y, h1, l1);
    *(ushort2*)(dh + (size_t)row * Wd + c2) = make_ushort2(h0, h1);
    *(ushort2*)(dl + (size_t)row * Wd + c2) = make_ushort2(l0, l1);
}

// ===========================================================================
// proj_mma: bf16x3 HMMA GEMM, cp.async double-buffered, K-chunk 32.
// pitch 40 ushorts (80B) -> conflict-free ldmatrix; 24 mainloop iterations.
// ===========================================================================
#define PP 40                          // smem pitch in ushorts (80B)
#define PROJ_TILE (128*PP)             // 5120 ushorts per array
#define PROJ_BUF  (4*PROJ_TILE)        // Ah|Al|Bh|Bl = 20480 ushorts
#define PROJ_SMEM (2*PROJ_BUF*2)       // 81920 bytes

__global__ __launch_bounds__(256, 2)
void proj_mma(int mode, const float* __restrict__ b0, const float* __restrict__ b1,
              const float* __restrict__ b2, float* __restrict__ out_ext) {
    extern __shared__ ushort psm[];

    const int t = threadIdx.x;
    const int wid = t >> 5;
    const int lane = t & 31;

    const ushort *Axh, *Axl, *Wxh, *Wxl;
    const float* bias;
    ushort *oh = nullptr, *ol = nullptr;
    if (mode == 1) {
        Axh = g_ch; Axl = g_cl;
        Wxh = g_wh + 3*WW; Wxl = g_wl + 3*WW;
        bias = b0;
    } else {
        Axh = g_xh; Axl = g_xl;
        const int z = blockIdx.z;
        Wxh = g_wh + z*WW; Wxl = g_wl + z*WW;
        bias = (z == 0) ? b0 : (z == 1) ? b1 : b2;
        if (z == 0)      { oh = g_qh; ol = g_ql; }
        else if (z == 1) { oh = g_kh; ol = g_kl; }
        else             { oh = g_vh; ol = g_vl; }
    }

    const int n0 = blockIdx.x * 128;
    const int i0 = blockIdx.y * 128;
    const int wm = (wid & 3) * 32;
    const int wn = (wid >> 2) * 64;

    const uint32_t sb = (uint32_t)__cvta_generic_to_shared(psm);

    const ushort* s4[4] = { Axh + (size_t)i0 * Wd,
                            Axl + (size_t)i0 * Wd,
                            Wxh + (size_t)n0 * Wd,
                            Wxl + (size_t)n0 * Wd };

    // 128 rows x 4 16B-chunks per array (32 k-values); 8 cp16 per thread.
    auto prefetch = [&](int c, int bsel) {
        const int k0 = c * 32;
        const uint32_t base = sb + bsel * (PROJ_BUF * 2);
        #pragma unroll
        for (int u = 0; u < 8; u++) {
            const int arr = u >> 1;
            const int id = ((u & 1) << 8) + t;     // 0..511
            const int row = id >> 2, ch = id & 3;
            cp16(base + (arr * PROJ_TILE + row * PP + ch * 8) * 2,
                 s4[arr] + (size_t)row * Wd + k0 + ch * 8);
        }
        CP_COMMIT();
    };

    float acc[2][8][4];
    #pragma unroll
    for (int mi = 0; mi < 2; mi++)
        #pragma unroll
        for (int ni = 0; ni < 8; ni++)
            #pragma unroll
            for (int j = 0; j < 4; j++) acc[mi][ni][j] = 0.f;

    const int frag_row = ((lane >> 3) & 1) * 8 + (lane & 7);
    const int frag_koff = (lane >> 4) * 16;
    const int bfrag_row = ((lane >> 4) & 1) * 8 + (lane & 7);
    const int bfrag_koff = ((lane >> 3) & 1) * 16;

    prefetch(0, 0);

    for (int c = 0; c < 24; c++) {
        if (c + 1 < 24) { prefetch(c + 1, (c + 1) & 1); CP_WAIT(1); }
        else            { CP_WAIT(0); }
        __syncthreads();

        const uint32_t bb = sb + (c & 1) * (PROJ_BUF * 2);
        const uint32_t a_base  = bb;
        const uint32_t al_base = bb + PROJ_TILE * 2;
        const uint32_t b_base  = bb + 2 * PROJ_TILE * 2;
        const uint32_t bl_base = bb + 3 * PROJ_TILE * 2;

        #pragma unroll
        for (int kb = 0; kb < 2; kb++) {
            uint32_t ah[2][4], alr[2][4];
            #pragma unroll
            for (int mi = 0; mi < 2; mi++) {
                const uint32_t off = (uint32_t)((wm + mi * 16 + frag_row) * (PP*2)
                                                + kb * 32 + frag_koff);
                ldsm_x4(ah[mi], a_base + off);
                ldsm_x4(alr[mi], al_base + off);
            }
            #pragma unroll
            for (int g = 0; g < 4; g++) {
                uint32_t bh[4], blr[4];
                const uint32_t off = (uint32_t)((wn + g * 16 + bfrag_row) * (PP*2)
                                                + kb * 32 + bfrag_koff);
                ldsm_x4(bh, b_base + off);
                ldsm_x4(blr, bl_base + off);
                #pragma unroll
                for (int s = 0; s < 2; s++) {
                    #pragma unroll
                    for (int mi = 0; mi < 2; mi++) {
                        float* cc = acc[mi][g * 2 + s];
                        mma_bf16(cc, ah[mi],  bh[2*s],  bh[2*s+1]);
                        mma_bf16(cc, ah[mi],  blr[2*s], blr[2*s+1]);
                        mma_bf16(cc, alr[mi], bh[2*s],  bh[2*s+1]);
                    }
                }
            }
        }
        __syncthreads();
    }

    #pragma unroll
    for (int mi = 0; mi < 2; mi++) {
        #pragma unroll
        for (int ni = 0; ni < 8; ni++) {
            const int row = i0 + wm + mi * 16 + (lane >> 2);
            const int col = n0 + wn + ni * 8 + (lane & 3) * 2;
            float2 bb2 = *(const float2*)(bias + col);
            float v0 = acc[mi][ni][0] + bb2.x, v1 = acc[mi][ni][1] + bb2.y;
            float v2 = acc[mi][ni][2] + bb2.x, v3 = acc[mi][ni][3] + bb2.y;
            if (mode == 1) {
                *(float2*)(out_ext + (size_t)row * Wd + col) = make_float2(v0, v1);
                *(float2*)(out_ext + (size_t)(row + 8) * Wd + col) = make_float2(v2, v3);
            } else {
                ushort h0,l0,h1,l1,h2,l2,h3,l3;
                split_bf(v0,h0,l0); split_bf(v1,h1,l1);
                split_bf(v2,h2,l2); split_bf(v3,h3,l3);
                *(ushort2*)(oh + (size_t)row * Wd + col) = make_ushort2(h0,h1);
                *(ushort2*)(ol + (size_t)row * Wd + col) = make_ushort2(l0,l1);
                *(ushort2*)(oh + (size_t)(row + 8) * Wd + col) = make_ushort2(h2,h3);
                *(ushort2*)(ol + (size_t)(row + 8) * Wd + col) = make_ushort2(l2,l3);
            }
        }
    }
}

// ===========================================================================
// Attention smem geometry (pitch 72 ushorts = 144B)
// ===========================================================================
#define PITCH 72
#define QT    (128*PITCH)
#define KT    (64*PITCH)

__device__ __forceinline__ void prefetch_q(uint32_t sb, const ushort* qh,
                                           const ushort* ql, int t) {
    #pragma unroll
    for (int u = 0; u < 8; u++) {
        const int arr = u >> 2;
        const int rem = ((u & 3) << 8) + t;
        const int row = rem >> 3, ch = rem & 7;
        const ushort* src = (arr == 0 ? qh : ql) + (size_t)row * Wd + ch * 8;
        cp16(sb + (arr * QT + row * PITCH + ch * 8) * 2, src);
    }
    CP_COMMIT();
}

// ===========================================================================
// attn_mma: FUSED two-pass fixed-base-softmax flash attention.
// ===========================================================================
#define AV_KVB (4*KT)
#define AV_SMEM ((2*QT + 2*AV_KVB)*2 + Sq*4)
__global__ __launch_bounds__(256, 2)
void attn_mma(const int* __restrict__ mask, float* __restrict__ attn_out) {
    extern __shared__ ushort smem_u[];
    float* MA = (float*)(smem_u + 2*QT + 2*AV_KVB);

    float* attnW = attn_out ? attn_out : g_attn_fallback;

    const int t = threadIdx.x;
    const int wid = t >> 5;
    const int lane = t & 31;
    const int z = blockIdx.y;
    const int b = z / Hh;
    const int h = z - b * Hh;
    const int i0 = blockIdx.x * 128;
    const int wm = wid * 16;

    const size_t qoff = ((size_t)b * Sq + i0) * Wd + h * Dd;
    const size_t koff = (size_t)b * Sq * Wd + h * Dd;

    const uint32_t sb = (uint32_t)__cvta_generic_to_shared(smem_u);

    auto prefetch_k = [&](int jt, int bsel) {
        const uint32_t base = sb + (2*QT + bsel * AV_KVB) * 2;
        const size_t off = koff + (size_t)jt * 64 * Wd;
        const ushort* s2[2] = { g_kh + off, g_kl + off };
        #pragma unroll
        for (int u = 0; u < 4; u++) {
            const int arr = u >> 1;
            const int rem = ((u & 1) << 8) + t;
            const int row = rem >> 3, ch = rem & 7;
            cp16(base + (arr * KT + row * PITCH + ch * 8) * 2,
                 s2[arr] + (size_t)row * Wd + ch * 8);
        }
        CP_COMMIT();
    };
    auto prefetch_kv = [&](int jt, int bsel) {
        const uint32_t base = sb + (2*QT + bsel * AV_KVB) * 2;
        const size_t off = koff + (size_t)jt * 64 * Wd;
        const ushort* s4[4] = { g_kh + off, g_kl + off, g_vh + off, g_vl + off };
        #pragma unroll
        for (int u = 0; u < 8; u++) {
            const int arr = u >> 1;
            const int rem = ((u & 1) << 8) + t;
            const int row = rem >> 3, ch = rem & 7;
            cp16(base + (arr * KT + row * PITCH + ch * 8) * 2,
                 s4[arr] + (size_t)row * Wd + ch * 8);
        }
        CP_COMMIT();
    };

    prefetch_q(sb, g_qh + qoff, g_ql + qoff, t);
    prefetch_k(0, 0);
    #pragma unroll
    for (int i = t; i < Sq; i += 256)
        MA[i] = __ldg(mask + b * Sq + i) ? 0.f : -1e9f;

    CP_WAIT(1);
    __syncthreads();

    const int frag_row = ((lane >> 3) & 1) * 8 + (lane & 7);
    const int frag_koff = (lane >> 4) * 16;
    const int bfrag_row = ((lane >> 4) & 1) * 8 + (lane & 7);
    const int bfrag_koff = ((lane >> 3) & 1) * 16;
    const int tfrag_row = ((lane >> 3) & 1) * 8 + (lane & 7);
    const int tfrag_noff = ((lane >> 4) & 1) * 16;

    uint32_t qh[4][4], ql[4][4];
    #pragma unroll
    for (int kb = 0; kb < 4; kb++) {
        const uint32_t off = (uint32_t)((wm + frag_row) * (PITCH * 2) + kb * 32 + frag_koff);
        ldsm_x4(qh[kb], sb + off);
        ldsm_x4(ql[kb], sb + QT * 2 + off);
    }

    // -------------------- Pass A: row sums of exp(score) --------------------
    float s0 = 0.f, s1 = 0.f;
    for (int jt = 0; jt < 16; jt++) {
        if (jt + 1 < 16) { prefetch_k(jt + 1, (jt + 1) & 1); CP_WAIT(1); }
        else             { CP_WAIT(0); }
        __syncthreads();

        const uint32_t kh_base = sb + (2*QT + (jt & 1) * AV_KVB) * 2;
        const uint32_t kl_base = kh_base + KT * 2;
        const int j0 = jt * 64;

        #pragma unroll
        for (int p = 0; p < 4; p++) {
            float acc[2][4] = {};
            #pragma unroll
            for (int kb = 0; kb < 4; kb++) {
                uint32_t kh[4], kl[4];
                const uint32_t off = (uint32_t)((p * 16 + bfrag_row) * (PITCH * 2) + kb * 32 + bfrag_koff);
                ldsm_x4(kh, kh_base + off);
                ldsm_x4(kl, kl_base + off);
                #pragma unroll
                for (int s = 0; s < 2; s++) {
                    mma_bf16(acc[s], qh[kb], kh[2*s], kh[2*s+1]);
                    mma_bf16(acc[s], qh[kb], kl[2*s], kl[2*s+1]);
                    mma_bf16(acc[s], ql[kb], kh[2*s], kh[2*s+1]);
                }
            }
            #pragma unroll
            for (int s = 0; s < 2; s++) {
                const int col = j0 + p * 16 + s * 8 + (lane & 3) * 2;
                const float ma0 = MA[col], ma1 = MA[col + 1];
                s0 += __expf(acc[s][0] * 0.125f + ma0) + __expf(acc[s][1] * 0.125f + ma1);
                s1 += __expf(acc[s][2] * 0.125f + ma0) + __expf(acc[s][3] * 0.125f + ma1);
            }
        }
        __syncthreads();
    }
    s0 += __shfl_xor_sync(0xffffffffu, s0, 1);
    s0 += __shfl_xor_sync(0xffffffffu, s0, 2);
    s1 += __shfl_xor_sync(0xffffffffu, s1, 1);
    s1 += __shfl_xor_sync(0xffffffffu, s1, 2);
    const float ii0 = 1.0f / s0;
    const float ii1 = 1.0f / s1;

    // -------------------- Pass B: write P, fused P@V ------------------------
    const int r0 = wm + (lane >> 2);
    float ctx[8][4];
    #pragma unroll
    for (int ni = 0; ni < 8; ni++)
        #pragma unroll
        for (int j = 0; j < 4; j++) ctx[ni][j] = 0.f;

    float* Prow0 = attnW + ((size_t)z * Sq + i0 + r0) * Sq;
    float* Prow1 = attnW + ((size_t)z * Sq + i0 + r0 + 8) * Sq;

    prefetch_kv(0, 0);

    for (int jt = 0; jt < 16; jt++) {
        if (jt + 1 < 16) { prefetch_kv(jt + 1, (jt + 1) & 1); CP_WAIT(1); }
        else             { CP_WAIT(0); }
        __syncthreads();

        const uint32_t kb0 = sb + (2*QT + (jt & 1) * AV_KVB) * 2;
        const uint32_t kh_base = kb0;
        const uint32_t kl_base = kb0 + KT * 2;
        const uint32_t vh_base = kb0 + 2 * KT * 2;
        const uint32_t vl_base = kb0 + 3 * KT * 2;
        const int j0 = jt * 64;

        #pragma unroll
        for (int p = 0; p < 4; p++) {
            float acc[2][4] = {};
            #pragma unroll
            for (int kb = 0; kb < 4; kb++) {
                uint32_t kh[4], kl[4];
                const uint32_t off = (uint32_t)((p * 16 + bfrag_row) * (PITCH * 2) + kb * 32 + bfrag_koff);
                ldsm_x4(kh, kh_base + off);
                ldsm_x4(kl, kl_base + off);
                #pragma unroll
                for (int s = 0; s < 2; s++) {
                    mma_bf16(acc[s], qh[kb], kh[2*s], kh[2*s+1]);
                    mma_bf16(acc[s], qh[kb], kl[2*s], kl[2*s+1]);
                    mma_bf16(acc[s], ql[kb], kh[2*s], kh[2*s+1]);
                }
            }
            uint32_t pfh[4], pfl[4];
            #pragma unroll
            for (int s = 0; s < 2; s++) {
                const int col = j0 + p * 16 + s * 8 + (lane & 3) * 2;
                const float ma0 = MA[col], ma1 = MA[col + 1];
                float p0 = __expf(acc[s][0] * 0.125f + ma0) * ii0;
                float p1 = __expf(acc[s][1] * 0.125f + ma1) * ii0;
                float p2 = __expf(acc[s][2] * 0.125f + ma0) * ii1;
                float p3 = __expf(acc[s][3] * 0.125f + ma1) * ii1;
                *(float2*)(Prow0 + col) = make_float2(p0, p1);
                *(float2*)(Prow1 + col) = make_float2(p2, p3);
                ushort h0,l0,h1,l1,h2,l2,h3,l3;
                split_bf(p0,h0,l0); split_bf(p1,h1,l1);
                split_bf(p2,h2,l2); split_bf(p3,h3,l3);
                pfh[s*2+0] = (uint32_t)h0 | ((uint32_t)h1 << 16);
                pfh[s*2+1] = (uint32_t)h2 | ((uint32_t)h3 << 16);
                pfl[s*2+0] = (uint32_t)l0 | ((uint32_t)l1 << 16);
                pfl[s*2+1] = (uint32_t)l2 | ((uint32_t)l3 << 16);
            }
            #pragma unroll
            for (int gv = 0; gv < 4; gv++) {
                uint32_t vh[4], vl[4];
                const uint32_t off = (uint32_t)((p * 16 + tfrag_row) * (PITCH * 2) + gv * 32 + tfrag_noff);
                ldsm_x4_t(vh, vh_base + off);
                ldsm_x4_t(vl, vl_base + off);
                #pragma unroll
                for (int s = 0; s < 2; s++) {
                    float* cc = ctx[gv * 2 + s];
                    mma_bf16(cc, pfh, vh[2*s], vh[2*s+1]);
                    mma_bf16(cc, pfh, vl[2*s], vl[2*s+1]);
                    mma_bf16(cc, pfl, vh[2*s], vh[2*s+1]);
                }
            }
        }
        __syncthreads();
    }

    #pragma unroll
    for (int ni = 0; ni < 8; ni++) {
        const int col = (ni >> 1) * 16 + (ni & 1) * 8 + (lane & 3) * 2;
        const size_t o0 = ((size_t)b * Sq + i0 + r0) * Wd + h * Dd + col;
        const size_t o1 = ((size_t)b * Sq + i0 + r0 + 8) * Wd + h * Dd + col;
        ushort h0,l0,h1,l1,h2,l2,h3,l3;
        split_bf(ctx[ni][0],h0,l0); split_bf(ctx[ni][1],h1,l1);
        split_bf(ctx[ni][2],h2,l2); split_bf(ctx[ni][3],h3,l3);
        *(ushort2*)(g_ch + o0) = make_ushort2(h0,h1);
        *(ushort2*)(g_cl + o0) = make_ushort2(l0,l1);
        *(ushort2*)(g_ch + o1) = make_ushort2(h2,h3);
        *(ushort2*)(g_cl + o1) = make_ushort2(l2,l3);
    }
}

// ---------------------------------------------------------------------------
extern "C" void kernel_launch(void* const* d_in, const int* in_sizes, int n_in,
                              void* d_out, int out_size) {
    const float* query = (const float*)d_in[0];
    const int*   mask  = (const int*)d_in[1];
    const float* q_w = (const float*)d_in[2];
    const float* q_b = (const float*)d_in[3];
    const float* k_w = (const float*)d_in[4];
    const float* k_b = (const float*)d_in[5];
    const float* v_w = (const float*)d_in[6];
    const float* v_b = (const float*)d_in[7];
    const float* o_w = (const float*)d_in[8];
    const float* o_b = (const float*)d_in[9];

    float* out = (float*)d_out;
    float* attn = ((long long)out_size >= OUT_ELEMS + ATTN_ELEMS) ? out + OUT_ELEMS : nullptr;

    cudaFuncSetAttribute(proj_mma, cudaFuncAttributeMaxDynamicSharedMemorySize, PROJ_SMEM);
    cudaFuncSetAttribute(attn_mma, cudaFuncAttributeMaxDynamicSharedMemorySize, AV_SMEM);
    cudaFuncSetAttribute(attn_mma, cudaFuncAttributePreferredSharedMemoryCarveout, 100);

    const int conv_blocks = (BSq * (Wd / 2) + 255) / 256;
    conv_kernel<<<dim3(conv_blocks, 5), 256>>>(query, q_w, k_w, v_w, o_w);
    proj_mma<<<dim3(6, 32, 3), 256, PROJ_SMEM>>>(0, q_b, k_b, v_b, nullptr);
    attn_mma<<<dim3(8, NZ), 256, AV_SMEM>>>(mask, attn);
    proj_mma<<<dim3(6, 32, 1), 256, PROJ_SMEM>>>(1, o_b, nullptr, nullptr, out);
}